// round 3
// baseline (speedup 1.0000x reference)
#include <cuda_runtime.h>
#include <math.h>
#include <stdint.h>

// Problem dims
#define Bn   64
#define Sn   512
#define En   512
#define Hn   256
#define G4   1024   // 4*H
#define HID  512
#define ATTn 256
#define Cn   10
#define Mrows 32768 // S*B == B*S

// ------------------------- scratch (static device globals) -------------------------
__device__ float g_gx[2][Sn][Bn][G4];          // 256 MB: precomputed input-gate projections
__device__ float g_wp[2][4][Hn / 4][Hn][4];    // 2 MB: w_hh repacked [dir][gate][kchunk][j][4] for coalesced LDG.128
__device__ float g_lstm[Bn][Sn][HID];          // 64 MB: bilstm output
__device__ float g_T[Mrows][ATTn];             // 32 MB: tanh(att1) activations
__device__ float g_scores[Bn * Sn];
__device__ float g_alpha[Bn * Sn];
__device__ float g_pooled[Bn][HID];

__device__ __forceinline__ float sigf(float x) { return 1.f / (1.f + expf(-x)); }

// ------------------------- w_hh repack -------------------------
// dest[dir][r][k/4][j][k%4] = w_hh_dir[(r*256 + j)*256 + k]
__global__ void prep_w_kernel(const float* __restrict__ whf, const float* __restrict__ whb) {
    int e = blockIdx.x * blockDim.x + threadIdx.x;   // over 2*1024*256 = 524288
    int dir = e >> 18;
    int rem = e & 262143;
    int r = rem >> 16;
    int j = (rem >> 8) & 255;
    int k = rem & 255;
    const float* W = dir ? whb : whf;
    g_wp[dir][r][k >> 2][j][k & 3] = W[(r * 256 + j) * 256 + k];
}

// ------------------------- GEMM 1: gx = gather(emb) @ w_ih^T + b_ih + b_hh -------------------------
// M=32768 (row = s*64+b), N=1024, K=512. BM=128, BN=128, BK=16, 256 threads, 8x8 microtile.
__global__ __launch_bounds__(256) void gemm_gx_kernel(
    const int* __restrict__ x, const float* __restrict__ emb,
    const float* __restrict__ wif, const float* __restrict__ bif, const float* __restrict__ bhf,
    const float* __restrict__ wib, const float* __restrict__ bib, const float* __restrict__ bhb)
{
    const int dir = blockIdx.z;
    const float* W  = dir ? wib : wif;
    const float* B1 = dir ? bib : bif;
    const float* B2 = dir ? bhb : bhf;
    float* OUT = &g_gx[dir][0][0][0];

    __shared__ float As[16][128];
    __shared__ float Ws[16][128];
    __shared__ int   ridx[128];

    const int tid = threadIdx.x;
    const int m0 = blockIdx.x * 128;
    const int n0 = blockIdx.y * 128;

    if (tid < 128) {
        int r = m0 + tid;              // r = s*64 + b
        int s = r >> 6, b = r & 63;
        ridx[tid] = x[b * Sn + s];
    }
    __syncthreads();

    float acc[8][8];
    #pragma unroll
    for (int i = 0; i < 8; i++)
        #pragma unroll
        for (int j = 0; j < 8; j++) acc[i][j] = 0.f;

    const int rg = tid >> 4;   // 0..15
    const int cg = tid & 15;   // 0..15

    for (int k0 = 0; k0 < En; k0 += 16) {
        #pragma unroll
        for (int i = 0; i < 2; i++) {
            int e = tid + i * 256;               // 0..511 float4 slots
            int m = e >> 2;
            int k4 = (e & 3) * 4;
            float4 v = *reinterpret_cast<const float4*>(&emb[(size_t)ridx[m] * En + k0 + k4]);
            As[k4 + 0][m] = v.x; As[k4 + 1][m] = v.y; As[k4 + 2][m] = v.z; As[k4 + 3][m] = v.w;
        }
        #pragma unroll
        for (int i = 0; i < 2; i++) {
            int e = tid + i * 256;
            int n = e >> 2;
            int k4 = (e & 3) * 4;
            float4 v = *reinterpret_cast<const float4*>(&W[(size_t)(n0 + n) * En + k0 + k4]);
            Ws[k4 + 0][n] = v.x; Ws[k4 + 1][n] = v.y; Ws[k4 + 2][n] = v.z; Ws[k4 + 3][n] = v.w;
        }
        __syncthreads();
        #pragma unroll
        for (int k = 0; k < 16; k++) {
            float ra[8], rw[8];
            #pragma unroll
            for (int i = 0; i < 8; i++) ra[i] = As[k][rg * 8 + i];
            #pragma unroll
            for (int j = 0; j < 8; j++) rw[j] = Ws[k][cg * 8 + j];
            #pragma unroll
            for (int i = 0; i < 8; i++)
                #pragma unroll
                for (int j = 0; j < 8; j++) acc[i][j] += ra[i] * rw[j];
        }
        __syncthreads();
    }
    #pragma unroll
    for (int i = 0; i < 8; i++) {
        size_t r = (size_t)(m0 + rg * 8 + i);
        #pragma unroll
        for (int j = 0; j < 8; j++) {
            int n = n0 + cg * 8 + j;
            OUT[r * G4 + n] = acc[i][j] + B1[n] + B2[n];
        }
    }
}

// ------------------------- GEMM 2: T = tanh(lstm_out @ att1_w^T + b1) -------------------------
// M=32768 (row = b*512+s), N=256, K=512. Same template, no gather.
__global__ __launch_bounds__(256) void gemm_att_kernel(
    const float* __restrict__ W, const float* __restrict__ bias)
{
    __shared__ float As[16][128];
    __shared__ float Ws[16][128];

    const int tid = threadIdx.x;
    const int m0 = blockIdx.x * 128;
    const int n0 = blockIdx.y * 128;
    const float* A = &g_lstm[0][0][0];

    float acc[8][8];
    #pragma unroll
    for (int i = 0; i < 8; i++)
        #pragma unroll
        for (int j = 0; j < 8; j++) acc[i][j] = 0.f;

    const int rg = tid >> 4;
    const int cg = tid & 15;

    for (int k0 = 0; k0 < HID; k0 += 16) {
        #pragma unroll
        for (int i = 0; i < 2; i++) {
            int e = tid + i * 256;
            int m = e >> 2;
            int k4 = (e & 3) * 4;
            float4 v = *reinterpret_cast<const float4*>(&A[(size_t)(m0 + m) * HID + k0 + k4]);
            As[k4 + 0][m] = v.x; As[k4 + 1][m] = v.y; As[k4 + 2][m] = v.z; As[k4 + 3][m] = v.w;
        }
        #pragma unroll
        for (int i = 0; i < 2; i++) {
            int e = tid + i * 256;
            int n = e >> 2;
            int k4 = (e & 3) * 4;
            float4 v = *reinterpret_cast<const float4*>(&W[(size_t)(n0 + n) * HID + k0 + k4]);
            Ws[k4 + 0][n] = v.x; Ws[k4 + 1][n] = v.y; Ws[k4 + 2][n] = v.z; Ws[k4 + 3][n] = v.w;
        }
        __syncthreads();
        #pragma unroll
        for (int k = 0; k < 16; k++) {
            float ra[8], rw[8];
            #pragma unroll
            for (int i = 0; i < 8; i++) ra[i] = As[k][rg * 8 + i];
            #pragma unroll
            for (int j = 0; j < 8; j++) rw[j] = Ws[k][cg * 8 + j];
            #pragma unroll
            for (int i = 0; i < 8; i++)
                #pragma unroll
                for (int j = 0; j < 8; j++) acc[i][j] += ra[i] * rw[j];
        }
        __syncthreads();
    }
    #pragma unroll
    for (int i = 0; i < 8; i++) {
        int r = m0 + rg * 8 + i;
        #pragma unroll
        for (int j = 0; j < 8; j++) {
            int n = n0 + cg * 8 + j;
            g_T[r][n] = tanhf(acc[i][j] + bias[n]);
        }
    }
}

// ------------------------- LSTM recurrence -------------------------
// grid (32 batch-pairs, 2 dirs), 256 threads. Thread tid == hidden unit j; owns gate rows
// {j, j+256, j+512, j+768} for 2 batches. h in smem (broadcast reads), c in registers.
// w_hh streamed from L2 via g_wp (coalesced 512B per warp per load group).
__global__ __launch_bounds__(256) void lstm_kernel()
{
    const int dir = blockIdx.y;
    const int b0 = blockIdx.x * 2;
    const int tid = threadIdx.x;

    __shared__ float hs[2][Hn];
    hs[0][tid] = 0.f;
    hs[1][tid] = 0.f;
    float c0 = 0.f, c1 = 0.f;
    __syncthreads();

    const float* __restrict__ gxbase = &g_gx[dir][0][0][0];
    const float4* __restrict__ wp[4];
    #pragma unroll
    for (int r = 0; r < 4; r++) wp[r] = reinterpret_cast<const float4*>(&g_wp[dir][r][0][0][0]);

    for (int t = 0; t < Sn; t++) {
        const int s = dir ? (Sn - 1 - t) : t;

        float acc[4][2];
        #pragma unroll
        for (int r = 0; r < 4; r++) { acc[r][0] = 0.f; acc[r][1] = 0.f; }

        #pragma unroll 2
        for (int kc = 0; kc < Hn / 4; kc++) {
            float4 h0 = *reinterpret_cast<const float4*>(&hs[0][kc * 4]);
            float4 h1 = *reinterpret_cast<const float4*>(&hs[1][kc * 4]);
            #pragma unroll
            for (int r = 0; r < 4; r++) {
                float4 w4 = __ldg(&wp[r][kc * Hn + tid]);
                acc[r][0] += w4.x * h0.x + w4.y * h0.y + w4.z * h0.z + w4.w * h0.w;
                acc[r][1] += w4.x * h1.x + w4.y * h1.y + w4.z * h1.z + w4.w * h1.w;
            }
        }

        const float* gx0 = gxbase + ((size_t)s * Bn + b0) * G4;
        const float* gx1 = gx0 + G4;

        float i0 = sigf(gx0[0 * Hn + tid] + acc[0][0]);
        float f0 = sigf(gx0[1 * Hn + tid] + acc[1][0]);
        float gg0 = tanhf(gx0[2 * Hn + tid] + acc[2][0]);
        float o0 = sigf(gx0[3 * Hn + tid] + acc[3][0]);
        c0 = f0 * c0 + i0 * gg0;
        float hn0 = o0 * tanhf(c0);

        float i1 = sigf(gx1[0 * Hn + tid] + acc[0][1]);
        float f1 = sigf(gx1[1 * Hn + tid] + acc[1][1]);
        float gg1 = tanhf(gx1[2 * Hn + tid] + acc[2][1]);
        float o1 = sigf(gx1[3 * Hn + tid] + acc[3][1]);
        c1 = f1 * c1 + i1 * gg1;
        float hn1 = o1 * tanhf(c1);

        g_lstm[b0 + 0][s][dir * Hn + tid] = hn0;
        g_lstm[b0 + 1][s][dir * Hn + tid] = hn1;

        __syncthreads();
        hs[0][tid] = hn0;
        hs[1][tid] = hn1;
        __syncthreads();
    }
}

// ------------------------- scores = T @ UT -------------------------
__global__ __launch_bounds__(256) void score_kernel(const float* __restrict__ UT)
{
    int row = blockIdx.x * 8 + (threadIdx.x >> 5);
    int lane = threadIdx.x & 31;
    float s = 0.f;
    #pragma unroll
    for (int i = 0; i < 8; i++) s += g_T[row][lane + i * 32] * UT[lane + i * 32];
    #pragma unroll
    for (int o = 16; o > 0; o >>= 1) s += __shfl_xor_sync(0xffffffffu, s, o);
    if (lane == 0) g_scores[row] = s;
}

// ------------------------- softmax over S per batch -------------------------
__global__ __launch_bounds__(512) void softmax_kernel(float* alpha_out)
{
    int b = blockIdx.x, s = threadIdx.x;
    float v = g_scores[b * Sn + s];
    __shared__ float red[16];

    float m = v;
    #pragma unroll
    for (int o = 16; o > 0; o >>= 1) m = fmaxf(m, __shfl_xor_sync(0xffffffffu, m, o));
    if ((s & 31) == 0) red[s >> 5] = m;
    __syncthreads();
    if (s < 32) {
        float t = (s < 16) ? red[s] : -3.4e38f;
        #pragma unroll
        for (int o = 8; o > 0; o >>= 1) t = fmaxf(t, __shfl_xor_sync(0xffffffffu, t, o));
        if (s == 0) red[0] = t;
    }
    __syncthreads();
    m = red[0];
    __syncthreads();

    float e = expf(v - m);
    float sum = e;
    #pragma unroll
    for (int o = 16; o > 0; o >>= 1) sum += __shfl_xor_sync(0xffffffffu, sum, o);
    if ((s & 31) == 0) red[s >> 5] = sum;
    __syncthreads();
    if (s < 32) {
        float t = (s < 16) ? red[s] : 0.f;
        #pragma unroll
        for (int o = 8; o > 0; o >>= 1) t += __shfl_xor_sync(0xffffffffu, t, o);
        if (s == 0) red[0] = t;
    }
    __syncthreads();
    float a = e / red[0];
    g_alpha[b * Sn + s] = a;
    if (alpha_out) alpha_out[b * Sn + s] = a;
}

// ------------------------- pooled = sum_s alpha[b,s] * lstm_out[b,s,:] -------------------------
__global__ __launch_bounds__(512) void pooled_kernel()
{
    int b = blockIdx.x, h = threadIdx.x;
    __shared__ float al[Sn];
    al[h] = g_alpha[b * Sn + h];
    __syncthreads();
    float acc = 0.f;
    #pragma unroll 8
    for (int s = 0; s < Sn; s++) acc += al[s] * g_lstm[b][s][h];
    g_pooled[b][h] = acc;
}

// ------------------------- logit = pooled @ att2_w^T + b2 -------------------------
__global__ __launch_bounds__(320) void logit_kernel(
    const float* __restrict__ w2, const float* __restrict__ b2, float* out)
{
    int b = blockIdx.x;
    int c = threadIdx.x >> 5;     // 0..9
    int lane = threadIdx.x & 31;
    float acc = 0.f;
    #pragma unroll
    for (int i = 0; i < 16; i++)
        acc += g_pooled[b][lane + i * 32] * w2[c * HID + lane + i * 32];
    #pragma unroll
    for (int o = 16; o > 0; o >>= 1) acc += __shfl_xor_sync(0xffffffffu, acc, o);
    if (lane == 0 && out) out[b * Cn + c] = acc + b2[c];
}

// ------------------------- launch -------------------------
extern "C" void kernel_launch(void* const* d_in, const int* in_sizes, int n_in,
                              void* d_out, int out_size)
{
    const int*   x   = (const int*)d_in[0];
    const float* emb = (const float*)d_in[1];
    const float* wif = (const float*)d_in[2];
    const float* whf = (const float*)d_in[3];
    const float* bif = (const float*)d_in[4];
    const float* bhf = (const float*)d_in[5];
    const float* wib = (const float*)d_in[6];
    const float* whb = (const float*)d_in[7];
    const float* bib = (const float*)d_in[8];
    const float* bhb = (const float*)d_in[9];
    const float* a1w = (const float*)d_in[10];
    const float* a1b = (const float*)d_in[11];
    const float* ut  = (const float*)d_in[12];
    const float* a2w = (const float*)d_in[13];
    const float* a2b = (const float*)d_in[14];
    float* out = (float*)d_out;

    // output layout: (logit[64*10], alpha[64*512]) flattened in tuple order
    float* logit_ptr = nullptr;
    float* alpha_ptr = nullptr;
    if (out_size >= Bn * Cn + Bn * Sn) { logit_ptr = out; alpha_ptr = out + Bn * Cn; }
    else if (out_size == Bn * Sn)      { alpha_ptr = out; }
    else                                { logit_ptr = out; }

    prep_w_kernel<<<2048, 256>>>(whf, whb);
    gemm_gx_kernel<<<dim3(Mrows / 128, G4 / 128, 2), 256>>>(x, emb, wif, bif, bhf, wib, bib, bhb);
    lstm_kernel<<<dim3(Bn / 2, 2), 256>>>();
    gemm_att_kernel<<<dim3(Mrows / 128, ATTn / 128), 256>>>(a1w, a1b);
    score_kernel<<<Mrows / 8, 256>>>(ut);
    softmax_kernel<<<Bn, 512>>>(alpha_ptr);
    pooled_kernel<<<Bn, 512>>>();
    logit_kernel<<<Bn, 320>>>(a2w, a2b, logit_ptr);
}

// round 4
// speedup vs baseline: 1.0029x; 1.0029x over previous
#include <cuda_runtime.h>
#include <math.h>
#include <stdint.h>

// Problem dims
#define Bn   64
#define Sn   512
#define En   512
#define Hn   256
#define G4   1024   // 4*H
#define HID  512
#define ATTn 256
#define Cn   10
#define Mrows 32768 // S*B == B*S

// ------------------------- scratch (static device globals) -------------------------
__device__ float g_gx[2][Sn][Bn][G4];          // 256 MB: precomputed input-gate projections
__device__ float g_wp[2][4][Hn / 4][Hn][4];    // 2 MB: w_hh repacked [dir][gate][kchunk][j][4] for coalesced LDG.128
__device__ float g_lstm[Bn][Sn][HID];          // 64 MB: bilstm output
__device__ float g_T[Mrows][ATTn];             // 32 MB: tanh(att1) activations
__device__ float g_scores[Bn * Sn];
__device__ float g_alpha[Bn * Sn];
__device__ float g_pooled[Bn][HID];

__device__ __forceinline__ float sigf(float x) { return 1.f / (1.f + expf(-x)); }

// ------------------------- w_hh repack -------------------------
// dest[dir][r][k/4][j][k%4] = w_hh_dir[(r*256 + j)*256 + k]
__global__ void prep_w_kernel(const float* __restrict__ whf, const float* __restrict__ whb) {
    int e = blockIdx.x * blockDim.x + threadIdx.x;   // over 2*1024*256 = 524288
    int dir = e >> 18;
    int rem = e & 262143;
    int r = rem >> 16;
    int j = (rem >> 8) & 255;
    int k = rem & 255;
    const float* W = dir ? whb : whf;
    g_wp[dir][r][k >> 2][j][k & 3] = W[(r * 256 + j) * 256 + k];
}

// ------------------------- GEMM 1: gx = gather(emb) @ w_ih^T + b_ih + b_hh -------------------------
// M=32768 (row = s*64+b), N=1024, K=512. BM=128, BN=128, BK=16, 256 threads, 8x8 microtile.
__global__ __launch_bounds__(256) void gemm_gx_kernel(
    const int* __restrict__ x, const float* __restrict__ emb,
    const float* __restrict__ wif, const float* __restrict__ bif, const float* __restrict__ bhf,
    const float* __restrict__ wib, const float* __restrict__ bib, const float* __restrict__ bhb)
{
    const int dir = blockIdx.z;
    const float* W  = dir ? wib : wif;
    const float* B1 = dir ? bib : bif;
    const float* B2 = dir ? bhb : bhf;
    float* OUT = &g_gx[dir][0][0][0];

    __shared__ float As[16][128];
    __shared__ float Ws[16][128];
    __shared__ int   ridx[128];

    const int tid = threadIdx.x;
    const int m0 = blockIdx.x * 128;
    const int n0 = blockIdx.y * 128;

    if (tid < 128) {
        int r = m0 + tid;              // r = s*64 + b
        int s = r >> 6, b = r & 63;
        ridx[tid] = x[b * Sn + s];
    }
    __syncthreads();

    float acc[8][8];
    #pragma unroll
    for (int i = 0; i < 8; i++)
        #pragma unroll
        for (int j = 0; j < 8; j++) acc[i][j] = 0.f;

    const int rg = tid >> 4;   // 0..15
    const int cg = tid & 15;   // 0..15

    for (int k0 = 0; k0 < En; k0 += 16) {
        #pragma unroll
        for (int i = 0; i < 2; i++) {
            int e = tid + i * 256;               // 0..511 float4 slots
            int m = e >> 2;
            int k4 = (e & 3) * 4;
            float4 v = *reinterpret_cast<const float4*>(&emb[(size_t)ridx[m] * En + k0 + k4]);
            As[k4 + 0][m] = v.x; As[k4 + 1][m] = v.y; As[k4 + 2][m] = v.z; As[k4 + 3][m] = v.w;
        }
        #pragma unroll
        for (int i = 0; i < 2; i++) {
            int e = tid + i * 256;
            int n = e >> 2;
            int k4 = (e & 3) * 4;
            float4 v = *reinterpret_cast<const float4*>(&W[(size_t)(n0 + n) * En + k0 + k4]);
            Ws[k4 + 0][n] = v.x; Ws[k4 + 1][n] = v.y; Ws[k4 + 2][n] = v.z; Ws[k4 + 3][n] = v.w;
        }
        __syncthreads();
        #pragma unroll
        for (int k = 0; k < 16; k++) {
            float ra[8], rw[8];
            #pragma unroll
            for (int i = 0; i < 8; i++) ra[i] = As[k][rg * 8 + i];
            #pragma unroll
            for (int j = 0; j < 8; j++) rw[j] = Ws[k][cg * 8 + j];
            #pragma unroll
            for (int i = 0; i < 8; i++)
                #pragma unroll
                for (int j = 0; j < 8; j++) acc[i][j] += ra[i] * rw[j];
        }
        __syncthreads();
    }
    #pragma unroll
    for (int i = 0; i < 8; i++) {
        size_t r = (size_t)(m0 + rg * 8 + i);
        #pragma unroll
        for (int j = 0; j < 8; j++) {
            int n = n0 + cg * 8 + j;
            OUT[r * G4 + n] = acc[i][j] + B1[n] + B2[n];
        }
    }
}

// ------------------------- GEMM 2: T = tanh(lstm_out @ att1_w^T + b1) -------------------------
// M=32768 (row = b*512+s), N=256, K=512. Same template, no gather.
__global__ __launch_bounds__(256) void gemm_att_kernel(
    const float* __restrict__ W, const float* __restrict__ bias)
{
    __shared__ float As[16][128];
    __shared__ float Ws[16][128];

    const int tid = threadIdx.x;
    const int m0 = blockIdx.x * 128;
    const int n0 = blockIdx.y * 128;
    const float* A = &g_lstm[0][0][0];

    float acc[8][8];
    #pragma unroll
    for (int i = 0; i < 8; i++)
        #pragma unroll
        for (int j = 0; j < 8; j++) acc[i][j] = 0.f;

    const int rg = tid >> 4;
    const int cg = tid & 15;

    for (int k0 = 0; k0 < HID; k0 += 16) {
        #pragma unroll
        for (int i = 0; i < 2; i++) {
            int e = tid + i * 256;
            int m = e >> 2;
            int k4 = (e & 3) * 4;
            float4 v = *reinterpret_cast<const float4*>(&A[(size_t)(m0 + m) * HID + k0 + k4]);
            As[k4 + 0][m] = v.x; As[k4 + 1][m] = v.y; As[k4 + 2][m] = v.z; As[k4 + 3][m] = v.w;
        }
        #pragma unroll
        for (int i = 0; i < 2; i++) {
            int e = tid + i * 256;
            int n = e >> 2;
            int k4 = (e & 3) * 4;
            float4 v = *reinterpret_cast<const float4*>(&W[(size_t)(n0 + n) * HID + k0 + k4]);
            Ws[k4 + 0][n] = v.x; Ws[k4 + 1][n] = v.y; Ws[k4 + 2][n] = v.z; Ws[k4 + 3][n] = v.w;
        }
        __syncthreads();
        #pragma unroll
        for (int k = 0; k < 16; k++) {
            float ra[8], rw[8];
            #pragma unroll
            for (int i = 0; i < 8; i++) ra[i] = As[k][rg * 8 + i];
            #pragma unroll
            for (int j = 0; j < 8; j++) rw[j] = Ws[k][cg * 8 + j];
            #pragma unroll
            for (int i = 0; i < 8; i++)
                #pragma unroll
                for (int j = 0; j < 8; j++) acc[i][j] += ra[i] * rw[j];
        }
        __syncthreads();
    }
    #pragma unroll
    for (int i = 0; i < 8; i++) {
        int r = m0 + rg * 8 + i;
        #pragma unroll
        for (int j = 0; j < 8; j++) {
            int n = n0 + cg * 8 + j;
            g_T[r][n] = tanhf(acc[i][j] + bias[n]);
        }
    }
}

// ------------------------- LSTM recurrence -------------------------
// grid (32 batch-pairs, 2 dirs), 256 threads. Thread tid == hidden unit j; owns gate rows
// {j, j+256, j+512, j+768} for 2 batches. h in smem (broadcast reads), c in registers.
// w_hh streamed from L2 via g_wp (coalesced 512B per warp per load group).
__global__ __launch_bounds__(256) void lstm_kernel()
{
    const int dir = blockIdx.y;
    const int b0 = blockIdx.x * 2;
    const int tid = threadIdx.x;

    __shared__ float hs[2][Hn];
    hs[0][tid] = 0.f;
    hs[1][tid] = 0.f;
    float c0 = 0.f, c1 = 0.f;
    __syncthreads();

    const float* __restrict__ gxbase = &g_gx[dir][0][0][0];
    const float4* __restrict__ wp[4];
    #pragma unroll
    for (int r = 0; r < 4; r++) wp[r] = reinterpret_cast<const float4*>(&g_wp[dir][r][0][0][0]);

    for (int t = 0; t < Sn; t++) {
        const int s = dir ? (Sn - 1 - t) : t;

        float acc[4][2];
        #pragma unroll
        for (int r = 0; r < 4; r++) { acc[r][0] = 0.f; acc[r][1] = 0.f; }

        #pragma unroll 2
        for (int kc = 0; kc < Hn / 4; kc++) {
            float4 h0 = *reinterpret_cast<const float4*>(&hs[0][kc * 4]);
            float4 h1 = *reinterpret_cast<const float4*>(&hs[1][kc * 4]);
            #pragma unroll
            for (int r = 0; r < 4; r++) {
                float4 w4 = __ldg(&wp[r][kc * Hn + tid]);
                acc[r][0] += w4.x * h0.x + w4.y * h0.y + w4.z * h0.z + w4.w * h0.w;
                acc[r][1] += w4.x * h1.x + w4.y * h1.y + w4.z * h1.z + w4.w * h1.w;
            }
        }

        const float* gx0 = gxbase + ((size_t)s * Bn + b0) * G4;
        const float* gx1 = gx0 + G4;

        float i0 = sigf(gx0[0 * Hn + tid] + acc[0][0]);
        float f0 = sigf(gx0[1 * Hn + tid] + acc[1][0]);
        float gg0 = tanhf(gx0[2 * Hn + tid] + acc[2][0]);
        float o0 = sigf(gx0[3 * Hn + tid] + acc[3][0]);
        c0 = f0 * c0 + i0 * gg0;
        float hn0 = o0 * tanhf(c0);

        float i1 = sigf(gx1[0 * Hn + tid] + acc[0][1]);
        float f1 = sigf(gx1[1 * Hn + tid] + acc[1][1]);
        float gg1 = tanhf(gx1[2 * Hn + tid] + acc[2][1]);
        float o1 = sigf(gx1[3 * Hn + tid] + acc[3][1]);
        c1 = f1 * c1 + i1 * gg1;
        float hn1 = o1 * tanhf(c1);

        g_lstm[b0 + 0][s][dir * Hn + tid] = hn0;
        g_lstm[b0 + 1][s][dir * Hn + tid] = hn1;

        __syncthreads();
        hs[0][tid] = hn0;
        hs[1][tid] = hn1;
        __syncthreads();
    }
}

// ------------------------- scores = T @ UT -------------------------
__global__ __launch_bounds__(256) void score_kernel(const float* __restrict__ UT)
{
    int row = blockIdx.x * 8 + (threadIdx.x >> 5);
    int lane = threadIdx.x & 31;
    float s = 0.f;
    #pragma unroll
    for (int i = 0; i < 8; i++) s += g_T[row][lane + i * 32] * UT[lane + i * 32];
    #pragma unroll
    for (int o = 16; o > 0; o >>= 1) s += __shfl_xor_sync(0xffffffffu, s, o);
    if (lane == 0) g_scores[row] = s;
}

// ------------------------- softmax over S per batch -------------------------
__global__ __launch_bounds__(512) void softmax_kernel(float* alpha_out)
{
    int b = blockIdx.x, s = threadIdx.x;
    float v = g_scores[b * Sn + s];
    __shared__ float red[16];

    float m = v;
    #pragma unroll
    for (int o = 16; o > 0; o >>= 1) m = fmaxf(m, __shfl_xor_sync(0xffffffffu, m, o));
    if ((s & 31) == 0) red[s >> 5] = m;
    __syncthreads();
    if (s < 32) {
        float t = (s < 16) ? red[s] : -3.4e38f;
        #pragma unroll
        for (int o = 8; o > 0; o >>= 1) t = fmaxf(t, __shfl_xor_sync(0xffffffffu, t, o));
        if (s == 0) red[0] = t;
    }
    __syncthreads();
    m = red[0];
    __syncthreads();

    float e = expf(v - m);
    float sum = e;
    #pragma unroll
    for (int o = 16; o > 0; o >>= 1) sum += __shfl_xor_sync(0xffffffffu, sum, o);
    if ((s & 31) == 0) red[s >> 5] = sum;
    __syncthreads();
    if (s < 32) {
        float t = (s < 16) ? red[s] : 0.f;
        #pragma unroll
        for (int o = 8; o > 0; o >>= 1) t += __shfl_xor_sync(0xffffffffu, t, o);
        if (s == 0) red[0] = t;
    }
    __syncthreads();
    float a = e / red[0];
    g_alpha[b * Sn + s] = a;
    if (alpha_out) alpha_out[b * Sn + s] = a;
}

// ------------------------- pooled = sum_s alpha[b,s] * lstm_out[b,s,:] -------------------------
__global__ __launch_bounds__(512) void pooled_kernel()
{
    int b = blockIdx.x, h = threadIdx.x;
    __shared__ float al[Sn];
    al[h] = g_alpha[b * Sn + h];
    __syncthreads();
    float acc = 0.f;
    #pragma unroll 8
    for (int s = 0; s < Sn; s++) acc += al[s] * g_lstm[b][s][h];
    g_pooled[b][h] = acc;
}

// ------------------------- logit = pooled @ att2_w^T + b2 -------------------------
__global__ __launch_bounds__(320) void logit_kernel(
    const float* __restrict__ w2, const float* __restrict__ b2, float* out)
{
    int b = blockIdx.x;
    int c = threadIdx.x >> 5;     // 0..9
    int lane = threadIdx.x & 31;
    float acc = 0.f;
    #pragma unroll
    for (int i = 0; i < 16; i++)
        acc += g_pooled[b][lane + i * 32] * w2[c * HID + lane + i * 32];
    #pragma unroll
    for (int o = 16; o > 0; o >>= 1) acc += __shfl_xor_sync(0xffffffffu, acc, o);
    if (lane == 0 && out) out[b * Cn + c] = acc + b2[c];
}

// ------------------------- launch -------------------------
extern "C" void kernel_launch(void* const* d_in, const int* in_sizes, int n_in,
                              void* d_out, int out_size)
{
    const int*   x   = (const int*)d_in[0];
    const float* emb = (const float*)d_in[1];
    const float* wif = (const float*)d_in[2];
    const float* whf = (const float*)d_in[3];
    const float* bif = (const float*)d_in[4];
    const float* bhf = (const float*)d_in[5];
    const float* wib = (const float*)d_in[6];
    const float* whb = (const float*)d_in[7];
    const float* bib = (const float*)d_in[8];
    const float* bhb = (const float*)d_in[9];
    const float* a1w = (const float*)d_in[10];
    const float* a1b = (const float*)d_in[11];
    const float* ut  = (const float*)d_in[12];
    const float* a2w = (const float*)d_in[13];
    const float* a2b = (const float*)d_in[14];
    float* out = (float*)d_out;

    // output layout: (logit[64*10], alpha[64*512]) flattened in tuple order
    float* logit_ptr = nullptr;
    float* alpha_ptr = nullptr;
    if (out_size >= Bn * Cn + Bn * Sn) { logit_ptr = out; alpha_ptr = out + Bn * Cn; }
    else if (out_size == Bn * Sn)      { alpha_ptr = out; }
    else                                { logit_ptr = out; }

    prep_w_kernel<<<2048, 256>>>(whf, whb);
    gemm_gx_kernel<<<dim3(Mrows / 128, G4 / 128, 2), 256>>>(x, emb, wif, bif, bhf, wib, bib, bhb);
    lstm_kernel<<<dim3(Bn / 2, 2), 256>>>();
    gemm_att_kernel<<<dim3(Mrows / 128, ATTn / 128), 256>>>(a1w, a1b);
    score_kernel<<<Mrows / 8, 256>>>(ut);
    softmax_kernel<<<Bn, 512>>>(alpha_ptr);
    pooled_kernel<<<Bn, 512>>>();
    logit_kernel<<<Bn, 320>>>(a2w, a2b, logit_ptr);
}

// round 5
// speedup vs baseline: 1.8800x; 1.8746x over previous
#include <cuda_runtime.h>
#include <math.h>
#include <stdint.h>

// Problem dims
#define Bn   64
#define Sn   512
#define En   512
#define Hn   256
#define G4   1024   // 4*H
#define HID  512
#define ATTn 256
#define Cn   10
#define Mrows 32768 // S*B == B*S
#define CLU  8      // cluster size for LSTM

// ------------------------- scratch (static device globals) -------------------------
__device__ float g_embed[Mrows][En];           // 64 MB: materialized gather
__device__ float g_gx[2][Sn][Bn][G4];          // 256 MB: precomputed input-gate projections
__device__ float g_lstm[Bn][Sn][HID];          // 64 MB: bilstm output
__device__ float g_T[Mrows][ATTn];             // 32 MB: tanh(att1) activations
__device__ float g_scores[Bn * Sn];
__device__ float g_alpha[Bn * Sn];
__device__ float g_pooled[Bn][HID];

__device__ __forceinline__ float sigf(float x) { return 1.f / (1.f + expf(-x)); }

__device__ __forceinline__ uint32_t smem_u32(const void* p) {
    return (uint32_t)__cvta_generic_to_shared(p);
}
__device__ __forceinline__ void fma2(unsigned long long& acc, unsigned long long a, unsigned long long b) {
    asm volatile("fma.rn.f32x2 %0, %1, %2, %0;" : "+l"(acc) : "l"(a), "l"(b));
}

// ------------------------- embedding gather: g_embed[s*64+b] = emb[x[b,s]] -------------------------
__global__ __launch_bounds__(128) void gather_kernel(const int* __restrict__ x,
                                                     const float* __restrict__ emb)
{
    int row = blockIdx.x;               // row = s*64 + b
    int s = row >> 6, b = row & 63;
    int v = x[b * Sn + s];
    const float4* src = (const float4*)&emb[(size_t)v * En];
    float4* dst = (float4*)&g_embed[row][0];
    dst[threadIdx.x] = src[threadIdx.x];   // 128 * 16B = 2KB row
}

// ------------------------- GEMM 1: gx = g_embed @ w_ih^T + b_ih + b_hh -------------------------
// M=32768 (row = s*64+b), N=1024, K=512. BM=128, BN=128, BK=16, 256 threads, 8x8 microtile.
// Grid: x = n-tile (8), y = m-stripe (256), z = dir  -> co-resident blocks share the A stripe in L2.
__global__ __launch_bounds__(256) void gemm_gx_kernel(
    const float* __restrict__ wif, const float* __restrict__ bif, const float* __restrict__ bhf,
    const float* __restrict__ wib, const float* __restrict__ bib, const float* __restrict__ bhb)
{
    const int dir = blockIdx.z;
    const float* W  = dir ? wib : wif;
    const float* B1 = dir ? bib : bif;
    const float* B2 = dir ? bhb : bhf;
    float* OUT = &g_gx[dir][0][0][0];

    __shared__ float As[16][128];
    __shared__ float Ws[16][128];

    const int tid = threadIdx.x;
    const int n0 = blockIdx.x * 128;
    const int m0 = blockIdx.y * 128;
    const float* A = &g_embed[0][0];

    float acc[8][8];
    #pragma unroll
    for (int i = 0; i < 8; i++)
        #pragma unroll
        for (int j = 0; j < 8; j++) acc[i][j] = 0.f;

    const int rg = tid >> 4;   // 0..15
    const int cg = tid & 15;   // 0..15

    for (int k0 = 0; k0 < En; k0 += 16) {
        #pragma unroll
        for (int i = 0; i < 2; i++) {
            int e = tid + i * 256;               // 0..511 float4 slots
            int m = e >> 2;
            int k4 = (e & 3) * 4;
            float4 v = *reinterpret_cast<const float4*>(&A[(size_t)(m0 + m) * En + k0 + k4]);
            As[k4 + 0][m] = v.x; As[k4 + 1][m] = v.y; As[k4 + 2][m] = v.z; As[k4 + 3][m] = v.w;
        }
        #pragma unroll
        for (int i = 0; i < 2; i++) {
            int e = tid + i * 256;
            int n = e >> 2;
            int k4 = (e & 3) * 4;
            float4 v = *reinterpret_cast<const float4*>(&W[(size_t)(n0 + n) * En + k0 + k4]);
            Ws[k4 + 0][n] = v.x; Ws[k4 + 1][n] = v.y; Ws[k4 + 2][n] = v.z; Ws[k4 + 3][n] = v.w;
        }
        __syncthreads();
        #pragma unroll
        for (int k = 0; k < 16; k++) {
            float ra[8], rw[8];
            #pragma unroll
            for (int i = 0; i < 8; i++) ra[i] = As[k][rg * 8 + i];
            #pragma unroll
            for (int j = 0; j < 8; j++) rw[j] = Ws[k][cg * 8 + j];
            #pragma unroll
            for (int i = 0; i < 8; i++)
                #pragma unroll
                for (int j = 0; j < 8; j++) acc[i][j] += ra[i] * rw[j];
        }
        __syncthreads();
    }
    #pragma unroll
    for (int i = 0; i < 8; i++) {
        size_t r = (size_t)(m0 + rg * 8 + i);
        #pragma unroll
        for (int j = 0; j < 8; j++) {
            int n = n0 + cg * 8 + j;
            OUT[r * G4 + n] = acc[i][j] + B1[n] + B2[n];
        }
    }
}

// ------------------------- GEMM 2: T = tanh(lstm_out @ att1_w^T + b1) -------------------------
__global__ __launch_bounds__(256) void gemm_att_kernel(
    const float* __restrict__ W, const float* __restrict__ bias)
{
    __shared__ float As[16][128];
    __shared__ float Ws[16][128];

    const int tid = threadIdx.x;
    const int m0 = blockIdx.x * 128;
    const int n0 = blockIdx.y * 128;
    const float* A = &g_lstm[0][0][0];

    float acc[8][8];
    #pragma unroll
    for (int i = 0; i < 8; i++)
        #pragma unroll
        for (int j = 0; j < 8; j++) acc[i][j] = 0.f;

    const int rg = tid >> 4;
    const int cg = tid & 15;

    for (int k0 = 0; k0 < HID; k0 += 16) {
        #pragma unroll
        for (int i = 0; i < 2; i++) {
            int e = tid + i * 256;
            int m = e >> 2;
            int k4 = (e & 3) * 4;
            float4 v = *reinterpret_cast<const float4*>(&A[(size_t)(m0 + m) * HID + k0 + k4]);
            As[k4 + 0][m] = v.x; As[k4 + 1][m] = v.y; As[k4 + 2][m] = v.z; As[k4 + 3][m] = v.w;
        }
        #pragma unroll
        for (int i = 0; i < 2; i++) {
            int e = tid + i * 256;
            int n = e >> 2;
            int k4 = (e & 3) * 4;
            float4 v = *reinterpret_cast<const float4*>(&W[(size_t)(n0 + n) * HID + k0 + k4]);
            Ws[k4 + 0][n] = v.x; Ws[k4 + 1][n] = v.y; Ws[k4 + 2][n] = v.z; Ws[k4 + 3][n] = v.w;
        }
        __syncthreads();
        #pragma unroll
        for (int k = 0; k < 16; k++) {
            float ra[8], rw[8];
            #pragma unroll
            for (int i = 0; i < 8; i++) ra[i] = As[k][rg * 8 + i];
            #pragma unroll
            for (int j = 0; j < 8; j++) rw[j] = Ws[k][cg * 8 + j];
            #pragma unroll
            for (int i = 0; i < 8; i++)
                #pragma unroll
                for (int j = 0; j < 8; j++) acc[i][j] += ra[i] * rw[j];
        }
        __syncthreads();
    }
    #pragma unroll
    for (int i = 0; i < 8; i++) {
        int r = m0 + rg * 8 + i;
        #pragma unroll
        for (int j = 0; j < 8; j++) {
            int n = n0 + cg * 8 + j;
            g_T[r][n] = tanhf(acc[i][j] + bias[n]);
        }
    }
}

// ------------------------- LSTM: cluster-persistent, SMEM-resident weights -------------------------
// grid = (64, 2): x = bg*8 + rank (cluster of 8 along x), y = dir. 256 threads.
// Cluster (dir, bg) handles 8 batches. CTA rank r owns hidden units j in [r*32, r*32+32),
// keeps its 4 gates x 32 j x 256 k weights (130 KB, padded) in SMEM, computes gates for its
// 8 batches with packed f32x2 FMA, then broadcasts its 32 h-values per batch to all 8 CTAs
// via DSMEM. One cluster barrier per step; h double-buffered.
//
// Thread layout: tid = b*32 + j  (warp == batch, lane == j). Weight LDS: per 8-lane phase,
// 8 consecutive j at row stride 130 u64 (=4 banks) -> 32 distinct banks, conflict-free.
// h LDS: whole warp reads the same address -> broadcast. gx LDG: 128B contiguous per warp.
#define LSTM_W_U64   (4 * 32 * 130)                       // padded weights, in u64
#define LSTM_SMEM    (LSTM_W_U64 * 8 + 2 * 8 * 256 * 4)   // 133120 + 16384 = 149504 B

__global__ __launch_bounds__(256, 1) __cluster_dims__(CLU, 1, 1)
void lstm_cluster_kernel(const float* __restrict__ whf, const float* __restrict__ whb)
{
    extern __shared__ unsigned long long sm[];
    unsigned long long (*w2)[32][130] = (unsigned long long(*)[32][130])sm;
    float* hb = (float*)(sm + LSTM_W_U64);    // hbuf[2][8][256]

    const int dir = blockIdx.y;
    const int cx  = blockIdx.x;
    const int bg  = cx >> 3;      // batch group 0..7
    const int r   = cx & 7;       // cluster rank
    const int tid = threadIdx.x;
    const int b   = tid >> 5;     // 0..7
    const int j   = tid & 31;     // 0..31

    // Load this CTA's weight slice: rows gate*256 + r*32 + jj, k = 0..255
    const float* W = dir ? whb : whf;
    for (int e = tid; e < 4 * 32 * 64; e += 256) {   // float4 granularity
        int g  = e >> 11;
        int jj = (e >> 6) & 31;
        int c4 = e & 63;
        float4 v = *(const float4*)&W[(size_t)(g * 256 + r * 32 + jj) * 256 + c4 * 4];
        *(float4*)&w2[g][jj][c4 * 2] = v;
    }
    for (int e = tid; e < 2 * 8 * 256; e += 256) hb[e] = 0.f;
    __syncthreads();
    asm volatile("barrier.cluster.arrive.aligned;" ::: "memory");
    asm volatile("barrier.cluster.wait.aligned;"  ::: "memory");

    // DSMEM destinations: peer hbuf base addresses
    uint32_t hb_local = smem_u32(hb);
    uint32_t dst[CLU];
    #pragma unroll
    for (int p = 0; p < CLU; p++) {
        uint32_t a;
        asm("mapa.shared::cluster.u32 %0, %1, %2;" : "=r"(a) : "r"(hb_local), "r"(p));
        dst[p] = a;
    }

    const unsigned long long* wrow0 = &w2[0][j][0];
    const unsigned long long* wrow1 = &w2[1][j][0];
    const unsigned long long* wrow2 = &w2[2][j][0];
    const unsigned long long* wrow3 = &w2[3][j][0];

    const int bglob = bg * 8 + b;
    const float* gxbase = &g_gx[dir][0][0][0];
    float c = 0.f;
    int cur = 0;

    for (int t = 0; t < Sn; t++) {
        const int s = dir ? (Sn - 1 - t) : t;

        // prefetch gx early (DRAM latency hidden under the acc loop)
        const float* gp = gxbase + ((size_t)s * Bn + bglob) * G4 + r * 32 + j;
        float pre_i = gp[0 * Hn], pre_f = gp[1 * Hn], pre_g = gp[2 * Hn], pre_o = gp[3 * Hn];

        const ulonglong2* hp = (const ulonglong2*)(hb + (cur * 8 + b) * 256);
        const ulonglong2* p0 = (const ulonglong2*)wrow0;
        const ulonglong2* p1 = (const ulonglong2*)wrow1;
        const ulonglong2* p2 = (const ulonglong2*)wrow2;
        const ulonglong2* p3 = (const ulonglong2*)wrow3;

        unsigned long long ai = 0ull, af = 0ull, ag = 0ull, ao = 0ull;
        #pragma unroll 8
        for (int kq = 0; kq < 64; kq++) {
            ulonglong2 h2 = hp[kq];
            ulonglong2 v0 = p0[kq];
            ulonglong2 v1 = p1[kq];
            ulonglong2 v2 = p2[kq];
            ulonglong2 v3 = p3[kq];
            fma2(ai, v0.x, h2.x); fma2(ai, v0.y, h2.y);
            fma2(af, v1.x, h2.x); fma2(af, v1.y, h2.y);
            fma2(ag, v2.x, h2.x); fma2(ag, v2.y, h2.y);
            fma2(ao, v3.x, h2.x); fma2(ao, v3.y, h2.y);
        }

        float2 qi = *(float2*)&ai, qf = *(float2*)&af, qg = *(float2*)&ag, qo = *(float2*)&ao;
        float I = sigf(pre_i + qi.x + qi.y);
        float F = sigf(pre_f + qf.x + qf.y);
        float G = tanhf(pre_g + qg.x + qg.y);
        float O = sigf(pre_o + qo.x + qo.y);
        c = F * c + I * G;
        float h = O * tanhf(c);

        g_lstm[bglob][s][dir * Hn + r * 32 + j] = h;

        const int nxt = cur ^ 1;
        uint32_t off = (uint32_t)(((nxt * 8 + b) * 256 + r * 32 + j) * 4);
        #pragma unroll
        for (int p = 0; p < CLU; p++)
            asm volatile("st.shared::cluster.f32 [%0], %1;" :: "r"(dst[p] + off), "f"(h) : "memory");

        asm volatile("barrier.cluster.arrive.aligned;" ::: "memory");
        asm volatile("barrier.cluster.wait.aligned;"  ::: "memory");
        cur = nxt;
    }
}

// ------------------------- scores = T @ UT -------------------------
__global__ __launch_bounds__(256) void score_kernel(const float* __restrict__ UT)
{
    int row = blockIdx.x * 8 + (threadIdx.x >> 5);
    int lane = threadIdx.x & 31;
    float s = 0.f;
    #pragma unroll
    for (int i = 0; i < 8; i++) s += g_T[row][lane + i * 32] * UT[lane + i * 32];
    #pragma unroll
    for (int o = 16; o > 0; o >>= 1) s += __shfl_xor_sync(0xffffffffu, s, o);
    if (lane == 0) g_scores[row] = s;
}

// ------------------------- softmax over S per batch -------------------------
__global__ __launch_bounds__(512) void softmax_kernel(float* alpha_out)
{
    int b = blockIdx.x, s = threadIdx.x;
    float v = g_scores[b * Sn + s];
    __shared__ float red[16];

    float m = v;
    #pragma unroll
    for (int o = 16; o > 0; o >>= 1) m = fmaxf(m, __shfl_xor_sync(0xffffffffu, m, o));
    if ((s & 31) == 0) red[s >> 5] = m;
    __syncthreads();
    if (s < 32) {
        float t = (s < 16) ? red[s] : -3.4e38f;
        #pragma unroll
        for (int o = 8; o > 0; o >>= 1) t = fmaxf(t, __shfl_xor_sync(0xffffffffu, t, o));
        if (s == 0) red[0] = t;
    }
    __syncthreads();
    m = red[0];
    __syncthreads();

    float e = expf(v - m);
    float sum = e;
    #pragma unroll
    for (int o = 16; o > 0; o >>= 1) sum += __shfl_xor_sync(0xffffffffu, sum, o);
    if ((s & 31) == 0) red[s >> 5] = sum;
    __syncthreads();
    if (s < 32) {
        float t = (s < 16) ? red[s] : 0.f;
        #pragma unroll
        for (int o = 8; o > 0; o >>= 1) t += __shfl_xor_sync(0xffffffffu, t, o);
        if (s == 0) red[0] = t;
    }
    __syncthreads();
    float a = e / red[0];
    g_alpha[b * Sn + s] = a;
    if (alpha_out) alpha_out[b * Sn + s] = a;
}

// ------------------------- pooled = sum_s alpha[b,s] * lstm_out[b,s,:] -------------------------
__global__ __launch_bounds__(512) void pooled_kernel()
{
    int b = blockIdx.x, h = threadIdx.x;
    __shared__ float al[Sn];
    al[h] = g_alpha[b * Sn + h];
    __syncthreads();
    float acc = 0.f;
    #pragma unroll 8
    for (int s = 0; s < Sn; s++) acc += al[s] * g_lstm[b][s][h];
    g_pooled[b][h] = acc;
}

// ------------------------- logit = pooled @ att2_w^T + b2 -------------------------
__global__ __launch_bounds__(320) void logit_kernel(
    const float* __restrict__ w2, const float* __restrict__ b2, float* out)
{
    int b = blockIdx.x;
    int c = threadIdx.x >> 5;     // 0..9
    int lane = threadIdx.x & 31;
    float acc = 0.f;
    #pragma unroll
    for (int i = 0; i < 16; i++)
        acc += g_pooled[b][lane + i * 32] * w2[c * HID + lane + i * 32];
    #pragma unroll
    for (int o = 16; o > 0; o >>= 1) acc += __shfl_xor_sync(0xffffffffu, acc, o);
    if (lane == 0 && out) out[b * Cn + c] = acc + b2[c];
}

// ------------------------- launch -------------------------
extern "C" void kernel_launch(void* const* d_in, const int* in_sizes, int n_in,
                              void* d_out, int out_size)
{
    const int*   x   = (const int*)d_in[0];
    const float* emb = (const float*)d_in[1];
    const float* wif = (const float*)d_in[2];
    const float* whf = (const float*)d_in[3];
    const float* bif = (const float*)d_in[4];
    const float* bhf = (const float*)d_in[5];
    const float* wib = (const float*)d_in[6];
    const float* whb = (const float*)d_in[7];
    const float* bib = (const float*)d_in[8];
    const float* bhb = (const float*)d_in[9];
    const float* a1w = (const float*)d_in[10];
    const float* a1b = (const float*)d_in[11];
    const float* ut  = (const float*)d_in[12];
    const float* a2w = (const float*)d_in[13];
    const float* a2b = (const float*)d_in[14];
    float* out = (float*)d_out;

    // output layout: (logit[64*10], alpha[64*512]) flattened in tuple order
    float* logit_ptr = nullptr;
    float* alpha_ptr = nullptr;
    if (out_size >= Bn * Cn + Bn * Sn) { logit_ptr = out; alpha_ptr = out + Bn * Cn; }
    else if (out_size == Bn * Sn)      { alpha_ptr = out; }
    else                                { logit_ptr = out; }

    static int smem_set = 0;
    if (!smem_set) {
        cudaFuncSetAttribute(lstm_cluster_kernel,
                             cudaFuncAttributeMaxDynamicSharedMemorySize, LSTM_SMEM);
        smem_set = 1;
    }

    gather_kernel<<<Mrows, 128>>>(x, emb);
    gemm_gx_kernel<<<dim3(G4 / 128, Mrows / 128, 2), 256>>>(wif, bif, bhf, wib, bib, bhb);
    lstm_cluster_kernel<<<dim3(64, 2), 256, LSTM_SMEM>>>(whf, whb);
    gemm_att_kernel<<<dim3(Mrows / 128, ATTn / 128), 256>>>(a1w, a1b);
    score_kernel<<<Mrows / 8, 256>>>(ut);
    softmax_kernel<<<Bn, 512>>>(alpha_ptr);
    pooled_kernel<<<Bn, 512>>>();
    logit_kernel<<<Bn, 320>>>(a2w, a2b, logit_ptr);
}

// round 6
// speedup vs baseline: 1.8802x; 1.0001x over previous
#include <cuda_runtime.h>
#include <math.h>
#include <stdint.h>

// Problem dims
#define Bn   64
#define Sn   512
#define En   512
#define Hn   256
#define G4   1024   // 4*H
#define HID  512
#define ATTn 256
#define Cn   10
#define Mrows 32768 // S*B == B*S
#define CLU  8      // cluster size for LSTM

// ------------------------- scratch (static device globals) -------------------------
__device__ float g_embed[Mrows][En];           // 64 MB: materialized gather
__device__ float g_gx[2][Sn][Bn][G4];          // 256 MB: precomputed input-gate projections
__device__ float g_lstm[Bn][Sn][HID];          // 64 MB: bilstm output
__device__ float g_T[Mrows][ATTn];             // 32 MB: tanh(att1) activations
__device__ float g_scores[Bn * Sn];
__device__ float g_alpha[Bn * Sn];
__device__ float g_pooled[Bn][HID];

__device__ __forceinline__ float sigf(float x) { return 1.f / (1.f + expf(-x)); }

__device__ __forceinline__ uint32_t smem_u32(const void* p) {
    return (uint32_t)__cvta_generic_to_shared(p);
}
__device__ __forceinline__ void fma2(unsigned long long& acc, unsigned long long a, unsigned long long b) {
    asm volatile("fma.rn.f32x2 %0, %1, %2, %0;" : "+l"(acc) : "l"(a), "l"(b));
}

// ------------------------- embedding gather: g_embed[s*64+b] = emb[x[b,s]] -------------------------
__global__ __launch_bounds__(128) void gather_kernel(const int* __restrict__ x,
                                                     const float* __restrict__ emb)
{
    int row = blockIdx.x;               // row = s*64 + b
    int s = row >> 6, b = row & 63;
    int v = x[b * Sn + s];
    const float4* src = (const float4*)&emb[(size_t)v * En];
    float4* dst = (float4*)&g_embed[row][0];
    dst[threadIdx.x] = src[threadIdx.x];   // 128 * 16B = 2KB row
}

// ------------------------- GEMM 1: gx = g_embed @ w_ih^T + b_ih + b_hh -------------------------
// M=32768 (row = s*64+b), N=1024, K=512. BM=128, BN=128, BK=16, 256 threads, 8x8 microtile.
// Grid: x = n-tile (8), y = m-stripe (256), z = dir  -> co-resident blocks share the A stripe in L2.
__global__ __launch_bounds__(256) void gemm_gx_kernel(
    const float* __restrict__ wif, const float* __restrict__ bif, const float* __restrict__ bhf,
    const float* __restrict__ wib, const float* __restrict__ bib, const float* __restrict__ bhb)
{
    const int dir = blockIdx.z;
    const float* W  = dir ? wib : wif;
    const float* B1 = dir ? bib : bif;
    const float* B2 = dir ? bhb : bhf;
    float* OUT = &g_gx[dir][0][0][0];

    __shared__ float As[16][128];
    __shared__ float Ws[16][128];

    const int tid = threadIdx.x;
    const int n0 = blockIdx.x * 128;
    const int m0 = blockIdx.y * 128;
    const float* A = &g_embed[0][0];

    float acc[8][8];
    #pragma unroll
    for (int i = 0; i < 8; i++)
        #pragma unroll
        for (int j = 0; j < 8; j++) acc[i][j] = 0.f;

    const int rg = tid >> 4;   // 0..15
    const int cg = tid & 15;   // 0..15

    for (int k0 = 0; k0 < En; k0 += 16) {
        #pragma unroll
        for (int i = 0; i < 2; i++) {
            int e = tid + i * 256;               // 0..511 float4 slots
            int m = e >> 2;
            int k4 = (e & 3) * 4;
            float4 v = *reinterpret_cast<const float4*>(&A[(size_t)(m0 + m) * En + k0 + k4]);
            As[k4 + 0][m] = v.x; As[k4 + 1][m] = v.y; As[k4 + 2][m] = v.z; As[k4 + 3][m] = v.w;
        }
        #pragma unroll
        for (int i = 0; i < 2; i++) {
            int e = tid + i * 256;
            int n = e >> 2;
            int k4 = (e & 3) * 4;
            float4 v = *reinterpret_cast<const float4*>(&W[(size_t)(n0 + n) * En + k0 + k4]);
            Ws[k4 + 0][n] = v.x; Ws[k4 + 1][n] = v.y; Ws[k4 + 2][n] = v.z; Ws[k4 + 3][n] = v.w;
        }
        __syncthreads();
        #pragma unroll
        for (int k = 0; k < 16; k++) {
            float ra[8], rw[8];
            #pragma unroll
            for (int i = 0; i < 8; i++) ra[i] = As[k][rg * 8 + i];
            #pragma unroll
            for (int j = 0; j < 8; j++) rw[j] = Ws[k][cg * 8 + j];
            #pragma unroll
            for (int i = 0; i < 8; i++)
                #pragma unroll
                for (int j = 0; j < 8; j++) acc[i][j] += ra[i] * rw[j];
        }
        __syncthreads();
    }
    #pragma unroll
    for (int i = 0; i < 8; i++) {
        size_t r = (size_t)(m0 + rg * 8 + i);
        #pragma unroll
        for (int j = 0; j < 8; j++) {
            int n = n0 + cg * 8 + j;
            OUT[r * G4 + n] = acc[i][j] + B1[n] + B2[n];
        }
    }
}

// ------------------------- GEMM 2: T = tanh(lstm_out @ att1_w^T + b1) -------------------------
__global__ __launch_bounds__(256) void gemm_att_kernel(
    const float* __restrict__ W, const float* __restrict__ bias)
{
    __shared__ float As[16][128];
    __shared__ float Ws[16][128];

    const int tid = threadIdx.x;
    const int m0 = blockIdx.x * 128;
    const int n0 = blockIdx.y * 128;
    const float* A = &g_lstm[0][0][0];

    float acc[8][8];
    #pragma unroll
    for (int i = 0; i < 8; i++)
        #pragma unroll
        for (int j = 0; j < 8; j++) acc[i][j] = 0.f;

    const int rg = tid >> 4;
    const int cg = tid & 15;

    for (int k0 = 0; k0 < HID; k0 += 16) {
        #pragma unroll
        for (int i = 0; i < 2; i++) {
            int e = tid + i * 256;
            int m = e >> 2;
            int k4 = (e & 3) * 4;
            float4 v = *reinterpret_cast<const float4*>(&A[(size_t)(m0 + m) * HID + k0 + k4]);
            As[k4 + 0][m] = v.x; As[k4 + 1][m] = v.y; As[k4 + 2][m] = v.z; As[k4 + 3][m] = v.w;
        }
        #pragma unroll
        for (int i = 0; i < 2; i++) {
            int e = tid + i * 256;
            int n = e >> 2;
            int k4 = (e & 3) * 4;
            float4 v = *reinterpret_cast<const float4*>(&W[(size_t)(n0 + n) * HID + k0 + k4]);
            Ws[k4 + 0][n] = v.x; Ws[k4 + 1][n] = v.y; Ws[k4 + 2][n] = v.z; Ws[k4 + 3][n] = v.w;
        }
        __syncthreads();
        #pragma unroll
        for (int k = 0; k < 16; k++) {
            float ra[8], rw[8];
            #pragma unroll
            for (int i = 0; i < 8; i++) ra[i] = As[k][rg * 8 + i];
            #pragma unroll
            for (int j = 0; j < 8; j++) rw[j] = Ws[k][cg * 8 + j];
            #pragma unroll
            for (int i = 0; i < 8; i++)
                #pragma unroll
                for (int j = 0; j < 8; j++) acc[i][j] += ra[i] * rw[j];
        }
        __syncthreads();
    }
    #pragma unroll
    for (int i = 0; i < 8; i++) {
        int r = m0 + rg * 8 + i;
        #pragma unroll
        for (int j = 0; j < 8; j++) {
            int n = n0 + cg * 8 + j;
            g_T[r][n] = tanhf(acc[i][j] + bias[n]);
        }
    }
}

// ------------------------- LSTM: cluster-persistent, SMEM-resident weights -------------------------
// grid = (64, 2): x = bg*8 + rank (cluster of 8 along x), y = dir. 256 threads.
// Cluster (dir, bg) handles 8 batches. CTA rank r owns hidden units j in [r*32, r*32+32),
// keeps its 4 gates x 32 j x 256 k weights (130 KB, padded) in SMEM, computes gates for its
// 8 batches with packed f32x2 FMA, then broadcasts its 32 h-values per batch to all 8 CTAs
// via DSMEM. One cluster barrier per step; h double-buffered.
//
// Thread layout: tid = b*32 + j  (warp == batch, lane == j). Weight LDS: per 8-lane phase,
// 8 consecutive j at row stride 130 u64 (=4 banks) -> 32 distinct banks, conflict-free.
// h LDS: whole warp reads the same address -> broadcast. gx LDG: 128B contiguous per warp.
#define LSTM_W_U64   (4 * 32 * 130)                       // padded weights, in u64
#define LSTM_SMEM    (LSTM_W_U64 * 8 + 2 * 8 * 256 * 4)   // 133120 + 16384 = 149504 B

__global__ __launch_bounds__(256, 1) __cluster_dims__(CLU, 1, 1)
void lstm_cluster_kernel(const float* __restrict__ whf, const float* __restrict__ whb)
{
    extern __shared__ unsigned long long sm[];
    unsigned long long (*w2)[32][130] = (unsigned long long(*)[32][130])sm;
    float* hb = (float*)(sm + LSTM_W_U64);    // hbuf[2][8][256]

    const int dir = blockIdx.y;
    const int cx  = blockIdx.x;
    const int bg  = cx >> 3;      // batch group 0..7
    const int r   = cx & 7;       // cluster rank
    const int tid = threadIdx.x;
    const int b   = tid >> 5;     // 0..7
    const int j   = tid & 31;     // 0..31

    // Load this CTA's weight slice: rows gate*256 + r*32 + jj, k = 0..255
    const float* W = dir ? whb : whf;
    for (int e = tid; e < 4 * 32 * 64; e += 256) {   // float4 granularity
        int g  = e >> 11;
        int jj = (e >> 6) & 31;
        int c4 = e & 63;
        float4 v = *(const float4*)&W[(size_t)(g * 256 + r * 32 + jj) * 256 + c4 * 4];
        *(float4*)&w2[g][jj][c4 * 2] = v;
    }
    for (int e = tid; e < 2 * 8 * 256; e += 256) hb[e] = 0.f;
    __syncthreads();
    asm volatile("barrier.cluster.arrive.aligned;" ::: "memory");
    asm volatile("barrier.cluster.wait.aligned;"  ::: "memory");

    // DSMEM destinations: peer hbuf base addresses
    uint32_t hb_local = smem_u32(hb);
    uint32_t dst[CLU];
    #pragma unroll
    for (int p = 0; p < CLU; p++) {
        uint32_t a;
        asm("mapa.shared::cluster.u32 %0, %1, %2;" : "=r"(a) : "r"(hb_local), "r"(p));
        dst[p] = a;
    }

    const unsigned long long* wrow0 = &w2[0][j][0];
    const unsigned long long* wrow1 = &w2[1][j][0];
    const unsigned long long* wrow2 = &w2[2][j][0];
    const unsigned long long* wrow3 = &w2[3][j][0];

    const int bglob = bg * 8 + b;
    const float* gxbase = &g_gx[dir][0][0][0];
    float c = 0.f;
    int cur = 0;

    for (int t = 0; t < Sn; t++) {
        const int s = dir ? (Sn - 1 - t) : t;

        // prefetch gx early (DRAM latency hidden under the acc loop)
        const float* gp = gxbase + ((size_t)s * Bn + bglob) * G4 + r * 32 + j;
        float pre_i = gp[0 * Hn], pre_f = gp[1 * Hn], pre_g = gp[2 * Hn], pre_o = gp[3 * Hn];

        const ulonglong2* hp = (const ulonglong2*)(hb + (cur * 8 + b) * 256);
        const ulonglong2* p0 = (const ulonglong2*)wrow0;
        const ulonglong2* p1 = (const ulonglong2*)wrow1;
        const ulonglong2* p2 = (const ulonglong2*)wrow2;
        const ulonglong2* p3 = (const ulonglong2*)wrow3;

        unsigned long long ai = 0ull, af = 0ull, ag = 0ull, ao = 0ull;
        #pragma unroll 8
        for (int kq = 0; kq < 64; kq++) {
            ulonglong2 h2 = hp[kq];
            ulonglong2 v0 = p0[kq];
            ulonglong2 v1 = p1[kq];
            ulonglong2 v2 = p2[kq];
            ulonglong2 v3 = p3[kq];
            fma2(ai, v0.x, h2.x); fma2(ai, v0.y, h2.y);
            fma2(af, v1.x, h2.x); fma2(af, v1.y, h2.y);
            fma2(ag, v2.x, h2.x); fma2(ag, v2.y, h2.y);
            fma2(ao, v3.x, h2.x); fma2(ao, v3.y, h2.y);
        }

        float2 qi = *(float2*)&ai, qf = *(float2*)&af, qg = *(float2*)&ag, qo = *(float2*)&ao;
        float I = sigf(pre_i + qi.x + qi.y);
        float F = sigf(pre_f + qf.x + qf.y);
        float G = tanhf(pre_g + qg.x + qg.y);
        float O = sigf(pre_o + qo.x + qo.y);
        c = F * c + I * G;
        float h = O * tanhf(c);

        g_lstm[bglob][s][dir * Hn + r * 32 + j] = h;

        const int nxt = cur ^ 1;
        uint32_t off = (uint32_t)(((nxt * 8 + b) * 256 + r * 32 + j) * 4);
        #pragma unroll
        for (int p = 0; p < CLU; p++)
            asm volatile("st.shared::cluster.f32 [%0], %1;" :: "r"(dst[p] + off), "f"(h) : "memory");

        asm volatile("barrier.cluster.arrive.aligned;" ::: "memory");
        asm volatile("barrier.cluster.wait.aligned;"  ::: "memory");
        cur = nxt;
    }
}

// ------------------------- scores = T @ UT -------------------------
__global__ __launch_bounds__(256) void score_kernel(const float* __restrict__ UT)
{
    int row = blockIdx.x * 8 + (threadIdx.x >> 5);
    int lane = threadIdx.x & 31;
    float s = 0.f;
    #pragma unroll
    for (int i = 0; i < 8; i++) s += g_T[row][lane + i * 32] * UT[lane + i * 32];
    #pragma unroll
    for (int o = 16; o > 0; o >>= 1) s += __shfl_xor_sync(0xffffffffu, s, o);
    if (lane == 0) g_scores[row] = s;
}

// ------------------------- softmax over S per batch -------------------------
__global__ __launch_bounds__(512) void softmax_kernel(float* alpha_out)
{
    int b = blockIdx.x, s = threadIdx.x;
    float v = g_scores[b * Sn + s];
    __shared__ float red[16];

    float m = v;
    #pragma unroll
    for (int o = 16; o > 0; o >>= 1) m = fmaxf(m, __shfl_xor_sync(0xffffffffu, m, o));
    if ((s & 31) == 0) red[s >> 5] = m;
    __syncthreads();
    if (s < 32) {
        float t = (s < 16) ? red[s] : -3.4e38f;
        #pragma unroll
        for (int o = 8; o > 0; o >>= 1) t = fmaxf(t, __shfl_xor_sync(0xffffffffu, t, o));
        if (s == 0) red[0] = t;
    }
    __syncthreads();
    m = red[0];
    __syncthreads();

    float e = expf(v - m);
    float sum = e;
    #pragma unroll
    for (int o = 16; o > 0; o >>= 1) sum += __shfl_xor_sync(0xffffffffu, sum, o);
    if ((s & 31) == 0) red[s >> 5] = sum;
    __syncthreads();
    if (s < 32) {
        float t = (s < 16) ? red[s] : 0.f;
        #pragma unroll
        for (int o = 8; o > 0; o >>= 1) t += __shfl_xor_sync(0xffffffffu, t, o);
        if (s == 0) red[0] = t;
    }
    __syncthreads();
    float a = e / red[0];
    g_alpha[b * Sn + s] = a;
    if (alpha_out) alpha_out[b * Sn + s] = a;
}

// ------------------------- pooled = sum_s alpha[b,s] * lstm_out[b,s,:] -------------------------
__global__ __launch_bounds__(512) void pooled_kernel()
{
    int b = blockIdx.x, h = threadIdx.x;
    __shared__ float al[Sn];
    al[h] = g_alpha[b * Sn + h];
    __syncthreads();
    float acc = 0.f;
    #pragma unroll 8
    for (int s = 0; s < Sn; s++) acc += al[s] * g_lstm[b][s][h];
    g_pooled[b][h] = acc;
}

// ------------------------- logit = pooled @ att2_w^T + b2 -------------------------
__global__ __launch_bounds__(320) void logit_kernel(
    const float* __restrict__ w2, const float* __restrict__ b2, float* out)
{
    int b = blockIdx.x;
    int c = threadIdx.x >> 5;     // 0..9
    int lane = threadIdx.x & 31;
    float acc = 0.f;
    #pragma unroll
    for (int i = 0; i < 16; i++)
        acc += g_pooled[b][lane + i * 32] * w2[c * HID + lane + i * 32];
    #pragma unroll
    for (int o = 16; o > 0; o >>= 1) acc += __shfl_xor_sync(0xffffffffu, acc, o);
    if (lane == 0 && out) out[b * Cn + c] = acc + b2[c];
}

// ------------------------- launch -------------------------
extern "C" void kernel_launch(void* const* d_in, const int* in_sizes, int n_in,
                              void* d_out, int out_size)
{
    const int*   x   = (const int*)d_in[0];
    const float* emb = (const float*)d_in[1];
    const float* wif = (const float*)d_in[2];
    const float* whf = (const float*)d_in[3];
    const float* bif = (const float*)d_in[4];
    const float* bhf = (const float*)d_in[5];
    const float* wib = (const float*)d_in[6];
    const float* whb = (const float*)d_in[7];
    const float* bib = (const float*)d_in[8];
    const float* bhb = (const float*)d_in[9];
    const float* a1w = (const float*)d_in[10];
    const float* a1b = (const float*)d_in[11];
    const float* ut  = (const float*)d_in[12];
    const float* a2w = (const float*)d_in[13];
    const float* a2b = (const float*)d_in[14];
    float* out = (float*)d_out;

    // output layout: (logit[64*10], alpha[64*512]) flattened in tuple order
    float* logit_ptr = nullptr;
    float* alpha_ptr = nullptr;
    if (out_size >= Bn * Cn + Bn * Sn) { logit_ptr = out; alpha_ptr = out + Bn * Cn; }
    else if (out_size == Bn * Sn)      { alpha_ptr = out; }
    else                                { logit_ptr = out; }

    static int smem_set = 0;
    if (!smem_set) {
        cudaFuncSetAttribute(lstm_cluster_kernel,
                             cudaFuncAttributeMaxDynamicSharedMemorySize, LSTM_SMEM);
        smem_set = 1;
    }

    gather_kernel<<<Mrows, 128>>>(x, emb);
    gemm_gx_kernel<<<dim3(G4 / 128, Mrows / 128, 2), 256>>>(wif, bif, bhf, wib, bib, bhb);
    lstm_cluster_kernel<<<dim3(64, 2), 256, LSTM_SMEM>>>(whf, whb);
    gemm_att_kernel<<<dim3(Mrows / 128, ATTn / 128), 256>>>(a1w, a1b);
    score_kernel<<<Mrows / 8, 256>>>(ut);
    softmax_kernel<<<Bn, 512>>>(alpha_ptr);
    pooled_kernel<<<Bn, 512>>>();
    logit_kernel<<<Bn, 320>>>(a2w, a2b, logit_ptr);
}

// round 7
// speedup vs baseline: 1.8807x; 1.0003x over previous
#include <cuda_runtime.h>
#include <math.h>
#include <stdint.h>

// Problem dims
#define Bn   64
#define Sn   512
#define En   512
#define Hn   256
#define G4   1024   // 4*H
#define HID  512
#define ATTn 256
#define Cn   10
#define Mrows 32768 // S*B == B*S
#define CLU  8      // cluster size for LSTM

// ------------------------- scratch (static device globals) -------------------------
__device__ float g_embed[Mrows][En];           // 64 MB: materialized gather
__device__ float g_gx[2][Sn][Bn][G4];          // 256 MB: precomputed input-gate projections
__device__ float g_lstm[Bn][Sn][HID];          // 64 MB: bilstm output
__device__ float g_T[Mrows][ATTn];             // 32 MB: tanh(att1) activations
__device__ float g_scores[Bn * Sn];
__device__ float g_alpha[Bn * Sn];
__device__ float g_pooled[Bn][HID];

__device__ __forceinline__ float sigf(float x) { return 1.f / (1.f + expf(-x)); }

__device__ __forceinline__ uint32_t smem_u32(const void* p) {
    return (uint32_t)__cvta_generic_to_shared(p);
}
__device__ __forceinline__ void fma2(unsigned long long& acc, unsigned long long a, unsigned long long b) {
    asm volatile("fma.rn.f32x2 %0, %1, %2, %0;" : "+l"(acc) : "l"(a), "l"(b));
}

// ------------------------- embedding gather: g_embed[s*64+b] = emb[x[b,s]] -------------------------
__global__ __launch_bounds__(128) void gather_kernel(const int* __restrict__ x,
                                                     const float* __restrict__ emb)
{
    int row = blockIdx.x;               // row = s*64 + b
    int s = row >> 6, b = row & 63;
    int v = x[b * Sn + s];
    const float4* src = (const float4*)&emb[(size_t)v * En];
    float4* dst = (float4*)&g_embed[row][0];
    dst[threadIdx.x] = src[threadIdx.x];   // 128 * 16B = 2KB row
}

// ------------------------- GEMM 1: gx = g_embed @ w_ih^T + b_ih + b_hh -------------------------
// M=32768 (row = s*64+b), N=1024, K=512. BM=128, BN=128, BK=16, 256 threads, 8x8 microtile.
// Grid: x = n-tile (8), y = m-stripe (256), z = dir  -> co-resident blocks share the A stripe in L2.
__global__ __launch_bounds__(256) void gemm_gx_kernel(
    const float* __restrict__ wif, const float* __restrict__ bif, const float* __restrict__ bhf,
    const float* __restrict__ wib, const float* __restrict__ bib, const float* __restrict__ bhb)
{
    const int dir = blockIdx.z;
    const float* W  = dir ? wib : wif;
    const float* B1 = dir ? bib : bif;
    const float* B2 = dir ? bhb : bhf;
    float* OUT = &g_gx[dir][0][0][0];

    __shared__ float As[16][128];
    __shared__ float Ws[16][128];

    const int tid = threadIdx.x;
    const int n0 = blockIdx.x * 128;
    const int m0 = blockIdx.y * 128;
    const float* A = &g_embed[0][0];

    float acc[8][8];
    #pragma unroll
    for (int i = 0; i < 8; i++)
        #pragma unroll
        for (int j = 0; j < 8; j++) acc[i][j] = 0.f;

    const int rg = tid >> 4;   // 0..15
    const int cg = tid & 15;   // 0..15

    for (int k0 = 0; k0 < En; k0 += 16) {
        #pragma unroll
        for (int i = 0; i < 2; i++) {
            int e = tid + i * 256;               // 0..511 float4 slots
            int m = e >> 2;
            int k4 = (e & 3) * 4;
            float4 v = *reinterpret_cast<const float4*>(&A[(size_t)(m0 + m) * En + k0 + k4]);
            As[k4 + 0][m] = v.x; As[k4 + 1][m] = v.y; As[k4 + 2][m] = v.z; As[k4 + 3][m] = v.w;
        }
        #pragma unroll
        for (int i = 0; i < 2; i++) {
            int e = tid + i * 256;
            int n = e >> 2;
            int k4 = (e & 3) * 4;
            float4 v = *reinterpret_cast<const float4*>(&W[(size_t)(n0 + n) * En + k0 + k4]);
            Ws[k4 + 0][n] = v.x; Ws[k4 + 1][n] = v.y; Ws[k4 + 2][n] = v.z; Ws[k4 + 3][n] = v.w;
        }
        __syncthreads();
        #pragma unroll
        for (int k = 0; k < 16; k++) {
            float ra[8], rw[8];
            #pragma unroll
            for (int i = 0; i < 8; i++) ra[i] = As[k][rg * 8 + i];
            #pragma unroll
            for (int j = 0; j < 8; j++) rw[j] = Ws[k][cg * 8 + j];
            #pragma unroll
            for (int i = 0; i < 8; i++)
                #pragma unroll
                for (int j = 0; j < 8; j++) acc[i][j] += ra[i] * rw[j];
        }
        __syncthreads();
    }
    #pragma unroll
    for (int i = 0; i < 8; i++) {
        size_t r = (size_t)(m0 + rg * 8 + i);
        #pragma unroll
        for (int j = 0; j < 8; j++) {
            int n = n0 + cg * 8 + j;
            OUT[r * G4 + n] = acc[i][j] + B1[n] + B2[n];
        }
    }
}

// ------------------------- GEMM 2: T = tanh(lstm_out @ att1_w^T + b1) -------------------------
__global__ __launch_bounds__(256) void gemm_att_kernel(
    const float* __restrict__ W, const float* __restrict__ bias)
{
    __shared__ float As[16][128];
    __shared__ float Ws[16][128];

    const int tid = threadIdx.x;
    const int m0 = blockIdx.x * 128;
    const int n0 = blockIdx.y * 128;
    const float* A = &g_lstm[0][0][0];

    float acc[8][8];
    #pragma unroll
    for (int i = 0; i < 8; i++)
        #pragma unroll
        for (int j = 0; j < 8; j++) acc[i][j] = 0.f;

    const int rg = tid >> 4;
    const int cg = tid & 15;

    for (int k0 = 0; k0 < HID; k0 += 16) {
        #pragma unroll
        for (int i = 0; i < 2; i++) {
            int e = tid + i * 256;
            int m = e >> 2;
            int k4 = (e & 3) * 4;
            float4 v = *reinterpret_cast<const float4*>(&A[(size_t)(m0 + m) * HID + k0 + k4]);
            As[k4 + 0][m] = v.x; As[k4 + 1][m] = v.y; As[k4 + 2][m] = v.z; As[k4 + 3][m] = v.w;
        }
        #pragma unroll
        for (int i = 0; i < 2; i++) {
            int e = tid + i * 256;
            int n = e >> 2;
            int k4 = (e & 3) * 4;
            float4 v = *reinterpret_cast<const float4*>(&W[(size_t)(n0 + n) * HID + k0 + k4]);
            Ws[k4 + 0][n] = v.x; Ws[k4 + 1][n] = v.y; Ws[k4 + 2][n] = v.z; Ws[k4 + 3][n] = v.w;
        }
        __syncthreads();
        #pragma unroll
        for (int k = 0; k < 16; k++) {
            float ra[8], rw[8];
            #pragma unroll
            for (int i = 0; i < 8; i++) ra[i] = As[k][rg * 8 + i];
            #pragma unroll
            for (int j = 0; j < 8; j++) rw[j] = Ws[k][cg * 8 + j];
            #pragma unroll
            for (int i = 0; i < 8; i++)
                #pragma unroll
                for (int j = 0; j < 8; j++) acc[i][j] += ra[i] * rw[j];
        }
        __syncthreads();
    }
    #pragma unroll
    for (int i = 0; i < 8; i++) {
        int r = m0 + rg * 8 + i;
        #pragma unroll
        for (int j = 0; j < 8; j++) {
            int n = n0 + cg * 8 + j;
            g_T[r][n] = tanhf(acc[i][j] + bias[n]);
        }
    }
}

// ------------------------- LSTM: cluster-persistent, SMEM-resident weights -------------------------
// grid = (64, 2): x = bg*8 + rank (cluster of 8 along x), y = dir. 256 threads.
// Cluster (dir, bg) handles 8 batches. CTA rank r owns hidden units j in [r*32, r*32+32),
// keeps its 4 gates x 32 j x 256 k weights (130 KB, padded) in SMEM, computes gates for its
// 8 batches with packed f32x2 FMA, then broadcasts its 32 h-values per batch to all 8 CTAs
// via DSMEM. One cluster barrier per step; h double-buffered.
//
// Thread layout: tid = b*32 + j  (warp == batch, lane == j). Weight LDS: per 8-lane phase,
// 8 consecutive j at row stride 130 u64 (=4 banks) -> 32 distinct banks, conflict-free.
// h LDS: whole warp reads the same address -> broadcast. gx LDG: 128B contiguous per warp.
#define LSTM_W_U64   (4 * 32 * 130)                       // padded weights, in u64
#define LSTM_SMEM    (LSTM_W_U64 * 8 + 2 * 8 * 256 * 4)   // 133120 + 16384 = 149504 B

__global__ __launch_bounds__(256, 1) __cluster_dims__(CLU, 1, 1)
void lstm_cluster_kernel(const float* __restrict__ whf, const float* __restrict__ whb)
{
    extern __shared__ unsigned long long sm[];
    unsigned long long (*w2)[32][130] = (unsigned long long(*)[32][130])sm;
    float* hb = (float*)(sm + LSTM_W_U64);    // hbuf[2][8][256]

    const int dir = blockIdx.y;
    const int cx  = blockIdx.x;
    const int bg  = cx >> 3;      // batch group 0..7
    const int r   = cx & 7;       // cluster rank
    const int tid = threadIdx.x;
    const int b   = tid >> 5;     // 0..7
    const int j   = tid & 31;     // 0..31

    // Load this CTA's weight slice: rows gate*256 + r*32 + jj, k = 0..255
    const float* W = dir ? whb : whf;
    for (int e = tid; e < 4 * 32 * 64; e += 256) {   // float4 granularity
        int g  = e >> 11;
        int jj = (e >> 6) & 31;
        int c4 = e & 63;
        float4 v = *(const float4*)&W[(size_t)(g * 256 + r * 32 + jj) * 256 + c4 * 4];
        *(float4*)&w2[g][jj][c4 * 2] = v;
    }
    for (int e = tid; e < 2 * 8 * 256; e += 256) hb[e] = 0.f;
    __syncthreads();
    asm volatile("barrier.cluster.arrive.aligned;" ::: "memory");
    asm volatile("barrier.cluster.wait.aligned;"  ::: "memory");

    // DSMEM destinations: peer hbuf base addresses
    uint32_t hb_local = smem_u32(hb);
    uint32_t dst[CLU];
    #pragma unroll
    for (int p = 0; p < CLU; p++) {
        uint32_t a;
        asm("mapa.shared::cluster.u32 %0, %1, %2;" : "=r"(a) : "r"(hb_local), "r"(p));
        dst[p] = a;
    }

    const unsigned long long* wrow0 = &w2[0][j][0];
    const unsigned long long* wrow1 = &w2[1][j][0];
    const unsigned long long* wrow2 = &w2[2][j][0];
    const unsigned long long* wrow3 = &w2[3][j][0];

    const int bglob = bg * 8 + b;
    const float* gxbase = &g_gx[dir][0][0][0];
    float c = 0.f;
    int cur = 0;

    for (int t = 0; t < Sn; t++) {
        const int s = dir ? (Sn - 1 - t) : t;

        // prefetch gx early (DRAM latency hidden under the acc loop)
        const float* gp = gxbase + ((size_t)s * Bn + bglob) * G4 + r * 32 + j;
        float pre_i = gp[0 * Hn], pre_f = gp[1 * Hn], pre_g = gp[2 * Hn], pre_o = gp[3 * Hn];

        const ulonglong2* hp = (const ulonglong2*)(hb + (cur * 8 + b) * 256);
        const ulonglong2* p0 = (const ulonglong2*)wrow0;
        const ulonglong2* p1 = (const ulonglong2*)wrow1;
        const ulonglong2* p2 = (const ulonglong2*)wrow2;
        const ulonglong2* p3 = (const ulonglong2*)wrow3;

        unsigned long long ai = 0ull, af = 0ull, ag = 0ull, ao = 0ull;
        #pragma unroll 8
        for (int kq = 0; kq < 64; kq++) {
            ulonglong2 h2 = hp[kq];
            ulonglong2 v0 = p0[kq];
            ulonglong2 v1 = p1[kq];
            ulonglong2 v2 = p2[kq];
            ulonglong2 v3 = p3[kq];
            fma2(ai, v0.x, h2.x); fma2(ai, v0.y, h2.y);
            fma2(af, v1.x, h2.x); fma2(af, v1.y, h2.y);
            fma2(ag, v2.x, h2.x); fma2(ag, v2.y, h2.y);
            fma2(ao, v3.x, h2.x); fma2(ao, v3.y, h2.y);
        }

        float2 qi = *(float2*)&ai, qf = *(float2*)&af, qg = *(float2*)&ag, qo = *(float2*)&ao;
        float I = sigf(pre_i + qi.x + qi.y);
        float F = sigf(pre_f + qf.x + qf.y);
        float G = tanhf(pre_g + qg.x + qg.y);
        float O = sigf(pre_o + qo.x + qo.y);
        c = F * c + I * G;
        float h = O * tanhf(c);

        g_lstm[bglob][s][dir * Hn + r * 32 + j] = h;

        const int nxt = cur ^ 1;
        uint32_t off = (uint32_t)(((nxt * 8 + b) * 256 + r * 32 + j) * 4);
        #pragma unroll
        for (int p = 0; p < CLU; p++)
            asm volatile("st.shared::cluster.f32 [%0], %1;" :: "r"(dst[p] + off), "f"(h) : "memory");

        asm volatile("barrier.cluster.arrive.aligned;" ::: "memory");
        asm volatile("barrier.cluster.wait.aligned;"  ::: "memory");
        cur = nxt;
    }
}

// ------------------------- scores = T @ UT -------------------------
__global__ __launch_bounds__(256) void score_kernel(const float* __restrict__ UT)
{
    int row = blockIdx.x * 8 + (threadIdx.x >> 5);
    int lane = threadIdx.x & 31;
    float s = 0.f;
    #pragma unroll
    for (int i = 0; i < 8; i++) s += g_T[row][lane + i * 32] * UT[lane + i * 32];
    #pragma unroll
    for (int o = 16; o > 0; o >>= 1) s += __shfl_xor_sync(0xffffffffu, s, o);
    if (lane == 0) g_scores[row] = s;
}

// ------------------------- softmax over S per batch -------------------------
__global__ __launch_bounds__(512) void softmax_kernel(float* alpha_out)
{
    int b = blockIdx.x, s = threadIdx.x;
    float v = g_scores[b * Sn + s];
    __shared__ float red[16];

    float m = v;
    #pragma unroll
    for (int o = 16; o > 0; o >>= 1) m = fmaxf(m, __shfl_xor_sync(0xffffffffu, m, o));
    if ((s & 31) == 0) red[s >> 5] = m;
    __syncthreads();
    if (s < 32) {
        float t = (s < 16) ? red[s] : -3.4e38f;
        #pragma unroll
        for (int o = 8; o > 0; o >>= 1) t = fmaxf(t, __shfl_xor_sync(0xffffffffu, t, o));
        if (s == 0) red[0] = t;
    }
    __syncthreads();
    m = red[0];
    __syncthreads();

    float e = expf(v - m);
    float sum = e;
    #pragma unroll
    for (int o = 16; o > 0; o >>= 1) sum += __shfl_xor_sync(0xffffffffu, sum, o);
    if ((s & 31) == 0) red[s >> 5] = sum;
    __syncthreads();
    if (s < 32) {
        float t = (s < 16) ? red[s] : 0.f;
        #pragma unroll
        for (int o = 8; o > 0; o >>= 1) t += __shfl_xor_sync(0xffffffffu, t, o);
        if (s == 0) red[0] = t;
    }
    __syncthreads();
    float a = e / red[0];
    g_alpha[b * Sn + s] = a;
    if (alpha_out) alpha_out[b * Sn + s] = a;
}

// ------------------------- pooled = sum_s alpha[b,s] * lstm_out[b,s,:] -------------------------
__global__ __launch_bounds__(512) void pooled_kernel()
{
    int b = blockIdx.x, h = threadIdx.x;
    __shared__ float al[Sn];
    al[h] = g_alpha[b * Sn + h];
    __syncthreads();
    float acc = 0.f;
    #pragma unroll 8
    for (int s = 0; s < Sn; s++) acc += al[s] * g_lstm[b][s][h];
    g_pooled[b][h] = acc;
}

// ------------------------- logit = pooled @ att2_w^T + b2 -------------------------
__global__ __launch_bounds__(320) void logit_kernel(
    const float* __restrict__ w2, const float* __restrict__ b2, float* out)
{
    int b = blockIdx.x;
    int c = threadIdx.x >> 5;     // 0..9
    int lane = threadIdx.x & 31;
    float acc = 0.f;
    #pragma unroll
    for (int i = 0; i < 16; i++)
        acc += g_pooled[b][lane + i * 32] * w2[c * HID + lane + i * 32];
    #pragma unroll
    for (int o = 16; o > 0; o >>= 1) acc += __shfl_xor_sync(0xffffffffu, acc, o);
    if (lane == 0 && out) out[b * Cn + c] = acc + b2[c];
}

// ------------------------- launch -------------------------
extern "C" void kernel_launch(void* const* d_in, const int* in_sizes, int n_in,
                              void* d_out, int out_size)
{
    const int*   x   = (const int*)d_in[0];
    const float* emb = (const float*)d_in[1];
    const float* wif = (const float*)d_in[2];
    const float* whf = (const float*)d_in[3];
    const float* bif = (const float*)d_in[4];
    const float* bhf = (const float*)d_in[5];
    const float* wib = (const float*)d_in[6];
    const float* whb = (const float*)d_in[7];
    const float* bib = (const float*)d_in[8];
    const float* bhb = (const float*)d_in[9];
    const float* a1w = (const float*)d_in[10];
    const float* a1b = (const float*)d_in[11];
    const float* ut  = (const float*)d_in[12];
    const float* a2w = (const float*)d_in[13];
    const float* a2b = (const float*)d_in[14];
    float* out = (float*)d_out;

    // output layout: (logit[64*10], alpha[64*512]) flattened in tuple order
    float* logit_ptr = nullptr;
    float* alpha_ptr = nullptr;
    if (out_size >= Bn * Cn + Bn * Sn) { logit_ptr = out; alpha_ptr = out + Bn * Cn; }
    else if (out_size == Bn * Sn)      { alpha_ptr = out; }
    else                                { logit_ptr = out; }

    static int smem_set = 0;
    if (!smem_set) {
        cudaFuncSetAttribute(lstm_cluster_kernel,
                             cudaFuncAttributeMaxDynamicSharedMemorySize, LSTM_SMEM);
        smem_set = 1;
    }

    gather_kernel<<<Mrows, 128>>>(x, emb);
    gemm_gx_kernel<<<dim3(G4 / 128, Mrows / 128, 2), 256>>>(wif, bif, bhf, wib, bib, bhb);
    lstm_cluster_kernel<<<dim3(64, 2), 256, LSTM_SMEM>>>(whf, whb);
    gemm_att_kernel<<<dim3(Mrows / 128, ATTn / 128), 256>>>(a1w, a1b);
    score_kernel<<<Mrows / 8, 256>>>(ut);
    softmax_kernel<<<Bn, 512>>>(alpha_ptr);
    pooled_kernel<<<Bn, 512>>>();
    logit_kernel<<<Bn, 320>>>(a2w, a2b, logit_ptr);
}

// round 8
// speedup vs baseline: 1.8810x; 1.0002x over previous
#include <cuda_runtime.h>
#include <math.h>
#include <stdint.h>

// Problem dims
#define Bn   64
#define Sn   512
#define En   512
#define Hn   256
#define G4   1024   // 4*H
#define HID  512
#define ATTn 256
#define Cn   10
#define Mrows 32768 // S*B == B*S
#define CLU  8      // cluster size for LSTM

// ------------------------- scratch (static device globals) -------------------------
__device__ float g_embed[Mrows][En];           // 64 MB: materialized gather
__device__ float g_gx[2][Sn][Bn][G4];          // 256 MB: precomputed input-gate projections
__device__ float g_lstm[Bn][Sn][HID];          // 64 MB: bilstm output
__device__ float g_T[Mrows][ATTn];             // 32 MB: tanh(att1) activations
__device__ float g_scores[Bn * Sn];
__device__ float g_alpha[Bn * Sn];
__device__ float g_pooled[Bn][HID];

__device__ __forceinline__ float sigf(float x) { return 1.f / (1.f + expf(-x)); }

__device__ __forceinline__ uint32_t smem_u32(const void* p) {
    return (uint32_t)__cvta_generic_to_shared(p);
}
__device__ __forceinline__ void fma2(unsigned long long& acc, unsigned long long a, unsigned long long b) {
    asm volatile("fma.rn.f32x2 %0, %1, %2, %0;" : "+l"(acc) : "l"(a), "l"(b));
}

// ------------------------- embedding gather: g_embed[s*64+b] = emb[x[b,s]] -------------------------
__global__ __launch_bounds__(128) void gather_kernel(const int* __restrict__ x,
                                                     const float* __restrict__ emb)
{
    int row = blockIdx.x;               // row = s*64 + b
    int s = row >> 6, b = row & 63;
    int v = x[b * Sn + s];
    const float4* src = (const float4*)&emb[(size_t)v * En];
    float4* dst = (float4*)&g_embed[row][0];
    dst[threadIdx.x] = src[threadIdx.x];   // 128 * 16B = 2KB row
}

// ------------------------- GEMM 1: gx = g_embed @ w_ih^T + b_ih + b_hh -------------------------
// M=32768 (row = s*64+b), N=1024, K=512. BM=128, BN=128, BK=16, 256 threads, 8x8 microtile.
// Grid: x = n-tile (8), y = m-stripe (256), z = dir  -> co-resident blocks share the A stripe in L2.
__global__ __launch_bounds__(256) void gemm_gx_kernel(
    const float* __restrict__ wif, const float* __restrict__ bif, const float* __restrict__ bhf,
    const float* __restrict__ wib, const float* __restrict__ bib, const float* __restrict__ bhb)
{
    const int dir = blockIdx.z;
    const float* W  = dir ? wib : wif;
    const float* B1 = dir ? bib : bif;
    const float* B2 = dir ? bhb : bhf;
    float* OUT = &g_gx[dir][0][0][0];

    __shared__ float As[16][128];
    __shared__ float Ws[16][128];

    const int tid = threadIdx.x;
    const int n0 = blockIdx.x * 128;
    const int m0 = blockIdx.y * 128;
    const float* A = &g_embed[0][0];

    float acc[8][8];
    #pragma unroll
    for (int i = 0; i < 8; i++)
        #pragma unroll
        for (int j = 0; j < 8; j++) acc[i][j] = 0.f;

    const int rg = tid >> 4;   // 0..15
    const int cg = tid & 15;   // 0..15

    for (int k0 = 0; k0 < En; k0 += 16) {
        #pragma unroll
        for (int i = 0; i < 2; i++) {
            int e = tid + i * 256;               // 0..511 float4 slots
            int m = e >> 2;
            int k4 = (e & 3) * 4;
            float4 v = *reinterpret_cast<const float4*>(&A[(size_t)(m0 + m) * En + k0 + k4]);
            As[k4 + 0][m] = v.x; As[k4 + 1][m] = v.y; As[k4 + 2][m] = v.z; As[k4 + 3][m] = v.w;
        }
        #pragma unroll
        for (int i = 0; i < 2; i++) {
            int e = tid + i * 256;
            int n = e >> 2;
            int k4 = (e & 3) * 4;
            float4 v = *reinterpret_cast<const float4*>(&W[(size_t)(n0 + n) * En + k0 + k4]);
            Ws[k4 + 0][n] = v.x; Ws[k4 + 1][n] = v.y; Ws[k4 + 2][n] = v.z; Ws[k4 + 3][n] = v.w;
        }
        __syncthreads();
        #pragma unroll
        for (int k = 0; k < 16; k++) {
            float ra[8], rw[8];
            #pragma unroll
            for (int i = 0; i < 8; i++) ra[i] = As[k][rg * 8 + i];
            #pragma unroll
            for (int j = 0; j < 8; j++) rw[j] = Ws[k][cg * 8 + j];
            #pragma unroll
            for (int i = 0; i < 8; i++)
                #pragma unroll
                for (int j = 0; j < 8; j++) acc[i][j] += ra[i] * rw[j];
        }
        __syncthreads();
    }
    #pragma unroll
    for (int i = 0; i < 8; i++) {
        size_t r = (size_t)(m0 + rg * 8 + i);
        #pragma unroll
        for (int j = 0; j < 8; j++) {
            int n = n0 + cg * 8 + j;
            OUT[r * G4 + n] = acc[i][j] + B1[n] + B2[n];
        }
    }
}

// ------------------------- GEMM 2: T = tanh(lstm_out @ att1_w^T + b1) -------------------------
__global__ __launch_bounds__(256) void gemm_att_kernel(
    const float* __restrict__ W, const float* __restrict__ bias)
{
    __shared__ float As[16][128];
    __shared__ float Ws[16][128];

    const int tid = threadIdx.x;
    const int m0 = blockIdx.x * 128;
    const int n0 = blockIdx.y * 128;
    const float* A = &g_lstm[0][0][0];

    float acc[8][8];
    #pragma unroll
    for (int i = 0; i < 8; i++)
        #pragma unroll
        for (int j = 0; j < 8; j++) acc[i][j] = 0.f;

    const int rg = tid >> 4;
    const int cg = tid & 15;

    for (int k0 = 0; k0 < HID; k0 += 16) {
        #pragma unroll
        for (int i = 0; i < 2; i++) {
            int e = tid + i * 256;
            int m = e >> 2;
            int k4 = (e & 3) * 4;
            float4 v = *reinterpret_cast<const float4*>(&A[(size_t)(m0 + m) * HID + k0 + k4]);
            As[k4 + 0][m] = v.x; As[k4 + 1][m] = v.y; As[k4 + 2][m] = v.z; As[k4 + 3][m] = v.w;
        }
        #pragma unroll
        for (int i = 0; i < 2; i++) {
            int e = tid + i * 256;
            int n = e >> 2;
            int k4 = (e & 3) * 4;
            float4 v = *reinterpret_cast<const float4*>(&W[(size_t)(n0 + n) * HID + k0 + k4]);
            Ws[k4 + 0][n] = v.x; Ws[k4 + 1][n] = v.y; Ws[k4 + 2][n] = v.z; Ws[k4 + 3][n] = v.w;
        }
        __syncthreads();
        #pragma unroll
        for (int k = 0; k < 16; k++) {
            float ra[8], rw[8];
            #pragma unroll
            for (int i = 0; i < 8; i++) ra[i] = As[k][rg * 8 + i];
            #pragma unroll
            for (int j = 0; j < 8; j++) rw[j] = Ws[k][cg * 8 + j];
            #pragma unroll
            for (int i = 0; i < 8; i++)
                #pragma unroll
                for (int j = 0; j < 8; j++) acc[i][j] += ra[i] * rw[j];
        }
        __syncthreads();
    }
    #pragma unroll
    for (int i = 0; i < 8; i++) {
        int r = m0 + rg * 8 + i;
        #pragma unroll
        for (int j = 0; j < 8; j++) {
            int n = n0 + cg * 8 + j;
            g_T[r][n] = tanhf(acc[i][j] + bias[n]);
        }
    }
}

// ------------------------- LSTM: cluster-persistent, SMEM-resident weights -------------------------
// grid = (64, 2): x = bg*8 + rank (cluster of 8 along x), y = dir. 256 threads.
// Cluster (dir, bg) handles 8 batches. CTA rank r owns hidden units j in [r*32, r*32+32),
// keeps its 4 gates x 32 j x 256 k weights (130 KB, padded) in SMEM, computes gates for its
// 8 batches with packed f32x2 FMA, then broadcasts its 32 h-values per batch to all 8 CTAs
// via DSMEM. One cluster barrier per step; h double-buffered.
//
// Thread layout: tid = b*32 + j  (warp == batch, lane == j). Weight LDS: per 8-lane phase,
// 8 consecutive j at row stride 130 u64 (=4 banks) -> 32 distinct banks, conflict-free.
// h LDS: whole warp reads the same address -> broadcast. gx LDG: 128B contiguous per warp.
#define LSTM_W_U64   (4 * 32 * 130)                       // padded weights, in u64
#define LSTM_SMEM    (LSTM_W_U64 * 8 + 2 * 8 * 256 * 4)   // 133120 + 16384 = 149504 B

__global__ __launch_bounds__(256, 1) __cluster_dims__(CLU, 1, 1)
void lstm_cluster_kernel(const float* __restrict__ whf, const float* __restrict__ whb)
{
    extern __shared__ unsigned long long sm[];
    unsigned long long (*w2)[32][130] = (unsigned long long(*)[32][130])sm;
    float* hb = (float*)(sm + LSTM_W_U64);    // hbuf[2][8][256]

    const int dir = blockIdx.y;
    const int cx  = blockIdx.x;
    const int bg  = cx >> 3;      // batch group 0..7
    const int r   = cx & 7;       // cluster rank
    const int tid = threadIdx.x;
    const int b   = tid >> 5;     // 0..7
    const int j   = tid & 31;     // 0..31

    // Load this CTA's weight slice: rows gate*256 + r*32 + jj, k = 0..255
    const float* W = dir ? whb : whf;
    for (int e = tid; e < 4 * 32 * 64; e += 256) {   // float4 granularity
        int g  = e >> 11;
        int jj = (e >> 6) & 31;
        int c4 = e & 63;
        float4 v = *(const float4*)&W[(size_t)(g * 256 + r * 32 + jj) * 256 + c4 * 4];
        *(float4*)&w2[g][jj][c4 * 2] = v;
    }
    for (int e = tid; e < 2 * 8 * 256; e += 256) hb[e] = 0.f;
    __syncthreads();
    asm volatile("barrier.cluster.arrive.aligned;" ::: "memory");
    asm volatile("barrier.cluster.wait.aligned;"  ::: "memory");

    // DSMEM destinations: peer hbuf base addresses
    uint32_t hb_local = smem_u32(hb);
    uint32_t dst[CLU];
    #pragma unroll
    for (int p = 0; p < CLU; p++) {
        uint32_t a;
        asm("mapa.shared::cluster.u32 %0, %1, %2;" : "=r"(a) : "r"(hb_local), "r"(p));
        dst[p] = a;
    }

    const unsigned long long* wrow0 = &w2[0][j][0];
    const unsigned long long* wrow1 = &w2[1][j][0];
    const unsigned long long* wrow2 = &w2[2][j][0];
    const unsigned long long* wrow3 = &w2[3][j][0];

    const int bglob = bg * 8 + b;
    const float* gxbase = &g_gx[dir][0][0][0];
    float c = 0.f;
    int cur = 0;

    for (int t = 0; t < Sn; t++) {
        const int s = dir ? (Sn - 1 - t) : t;

        // prefetch gx early (DRAM latency hidden under the acc loop)
        const float* gp = gxbase + ((size_t)s * Bn + bglob) * G4 + r * 32 + j;
        float pre_i = gp[0 * Hn], pre_f = gp[1 * Hn], pre_g = gp[2 * Hn], pre_o = gp[3 * Hn];

        const ulonglong2* hp = (const ulonglong2*)(hb + (cur * 8 + b) * 256);
        const ulonglong2* p0 = (const ulonglong2*)wrow0;
        const ulonglong2* p1 = (const ulonglong2*)wrow1;
        const ulonglong2* p2 = (const ulonglong2*)wrow2;
        const ulonglong2* p3 = (const ulonglong2*)wrow3;

        unsigned long long ai = 0ull, af = 0ull, ag = 0ull, ao = 0ull;
        #pragma unroll 8
        for (int kq = 0; kq < 64; kq++) {
            ulonglong2 h2 = hp[kq];
            ulonglong2 v0 = p0[kq];
            ulonglong2 v1 = p1[kq];
            ulonglong2 v2 = p2[kq];
            ulonglong2 v3 = p3[kq];
            fma2(ai, v0.x, h2.x); fma2(ai, v0.y, h2.y);
            fma2(af, v1.x, h2.x); fma2(af, v1.y, h2.y);
            fma2(ag, v2.x, h2.x); fma2(ag, v2.y, h2.y);
            fma2(ao, v3.x, h2.x); fma2(ao, v3.y, h2.y);
        }

        float2 qi = *(float2*)&ai, qf = *(float2*)&af, qg = *(float2*)&ag, qo = *(float2*)&ao;
        float I = sigf(pre_i + qi.x + qi.y);
        float F = sigf(pre_f + qf.x + qf.y);
        float G = tanhf(pre_g + qg.x + qg.y);
        float O = sigf(pre_o + qo.x + qo.y);
        c = F * c + I * G;
        float h = O * tanhf(c);

        g_lstm[bglob][s][dir * Hn + r * 32 + j] = h;

        const int nxt = cur ^ 1;
        uint32_t off = (uint32_t)(((nxt * 8 + b) * 256 + r * 32 + j) * 4);
        #pragma unroll
        for (int p = 0; p < CLU; p++)
            asm volatile("st.shared::cluster.f32 [%0], %1;" :: "r"(dst[p] + off), "f"(h) : "memory");

        asm volatile("barrier.cluster.arrive.aligned;" ::: "memory");
        asm volatile("barrier.cluster.wait.aligned;"  ::: "memory");
        cur = nxt;
    }
}

// ------------------------- scores = T @ UT -------------------------
__global__ __launch_bounds__(256) void score_kernel(const float* __restrict__ UT)
{
    int row = blockIdx.x * 8 + (threadIdx.x >> 5);
    int lane = threadIdx.x & 31;
    float s = 0.f;
    #pragma unroll
    for (int i = 0; i < 8; i++) s += g_T[row][lane + i * 32] * UT[lane + i * 32];
    #pragma unroll
    for (int o = 16; o > 0; o >>= 1) s += __shfl_xor_sync(0xffffffffu, s, o);
    if (lane == 0) g_scores[row] = s;
}

// ------------------------- softmax over S per batch -------------------------
__global__ __launch_bounds__(512) void softmax_kernel(float* alpha_out)
{
    int b = blockIdx.x, s = threadIdx.x;
    float v = g_scores[b * Sn + s];
    __shared__ float red[16];

    float m = v;
    #pragma unroll
    for (int o = 16; o > 0; o >>= 1) m = fmaxf(m, __shfl_xor_sync(0xffffffffu, m, o));
    if ((s & 31) == 0) red[s >> 5] = m;
    __syncthreads();
    if (s < 32) {
        float t = (s < 16) ? red[s] : -3.4e38f;
        #pragma unroll
        for (int o = 8; o > 0; o >>= 1) t = fmaxf(t, __shfl_xor_sync(0xffffffffu, t, o));
        if (s == 0) red[0] = t;
    }
    __syncthreads();
    m = red[0];
    __syncthreads();

    float e = expf(v - m);
    float sum = e;
    #pragma unroll
    for (int o = 16; o > 0; o >>= 1) sum += __shfl_xor_sync(0xffffffffu, sum, o);
    if ((s & 31) == 0) red[s >> 5] = sum;
    __syncthreads();
    if (s < 32) {
        float t = (s < 16) ? red[s] : 0.f;
        #pragma unroll
        for (int o = 8; o > 0; o >>= 1) t += __shfl_xor_sync(0xffffffffu, t, o);
        if (s == 0) red[0] = t;
    }
    __syncthreads();
    float a = e / red[0];
    g_alpha[b * Sn + s] = a;
    if (alpha_out) alpha_out[b * Sn + s] = a;
}

// ------------------------- pooled = sum_s alpha[b,s] * lstm_out[b,s,:] -------------------------
__global__ __launch_bounds__(512) void pooled_kernel()
{
    int b = blockIdx.x, h = threadIdx.x;
    __shared__ float al[Sn];
    al[h] = g_alpha[b * Sn + h];
    __syncthreads();
    float acc = 0.f;
    #pragma unroll 8
    for (int s = 0; s < Sn; s++) acc += al[s] * g_lstm[b][s][h];
    g_pooled[b][h] = acc;
}

// ------------------------- logit = pooled @ att2_w^T + b2 -------------------------
__global__ __launch_bounds__(320) void logit_kernel(
    const float* __restrict__ w2, const float* __restrict__ b2, float* out)
{
    int b = blockIdx.x;
    int c = threadIdx.x >> 5;     // 0..9
    int lane = threadIdx.x & 31;
    float acc = 0.f;
    #pragma unroll
    for (int i = 0; i < 16; i++)
        acc += g_pooled[b][lane + i * 32] * w2[c * HID + lane + i * 32];
    #pragma unroll
    for (int o = 16; o > 0; o >>= 1) acc += __shfl_xor_sync(0xffffffffu, acc, o);
    if (lane == 0 && out) out[b * Cn + c] = acc + b2[c];
}

// ------------------------- launch -------------------------
extern "C" void kernel_launch(void* const* d_in, const int* in_sizes, int n_in,
                              void* d_out, int out_size)
{
    const int*   x   = (const int*)d_in[0];
    const float* emb = (const float*)d_in[1];
    const float* wif = (const float*)d_in[2];
    const float* whf = (const float*)d_in[3];
    const float* bif = (const float*)d_in[4];
    const float* bhf = (const float*)d_in[5];
    const float* wib = (const float*)d_in[6];
    const float* whb = (const float*)d_in[7];
    const float* bib = (const float*)d_in[8];
    const float* bhb = (const float*)d_in[9];
    const float* a1w = (const float*)d_in[10];
    const float* a1b = (const float*)d_in[11];
    const float* ut  = (const float*)d_in[12];
    const float* a2w = (const float*)d_in[13];
    const float* a2b = (const float*)d_in[14];
    float* out = (float*)d_out;

    // output layout: (logit[64*10], alpha[64*512]) flattened in tuple order
    float* logit_ptr = nullptr;
    float* alpha_ptr = nullptr;
    if (out_size >= Bn * Cn + Bn * Sn) { logit_ptr = out; alpha_ptr = out + Bn * Cn; }
    else if (out_size == Bn * Sn)      { alpha_ptr = out; }
    else                                { logit_ptr = out; }

    static int smem_set = 0;
    if (!smem_set) {
        cudaFuncSetAttribute(lstm_cluster_kernel,
                             cudaFuncAttributeMaxDynamicSharedMemorySize, LSTM_SMEM);
        smem_set = 1;
    }

    gather_kernel<<<Mrows, 128>>>(x, emb);
    gemm_gx_kernel<<<dim3(G4 / 128, Mrows / 128, 2), 256>>>(wif, bif, bhf, wib, bib, bhb);
    lstm_cluster_kernel<<<dim3(64, 2), 256, LSTM_SMEM>>>(whf, whb);
    gemm_att_kernel<<<dim3(Mrows / 128, ATTn / 128), 256>>>(a1w, a1b);
    score_kernel<<<Mrows / 8, 256>>>(ut);
    softmax_kernel<<<Bn, 512>>>(alpha_ptr);
    pooled_kernel<<<Bn, 512>>>();
    logit_kernel<<<Bn, 320>>>(a2w, a2b, logit_ptr);
}

// round 9
// speedup vs baseline: 1.8818x; 1.0004x over previous
#include <cuda_runtime.h>
#include <math.h>
#include <stdint.h>

// Problem dims
#define Bn   64
#define Sn   512
#define En   512
#define Hn   256
#define G4   1024   // 4*H
#define HID  512
#define ATTn 256
#define Cn   10
#define Mrows 32768 // S*B == B*S
#define CLU  8      // cluster size for LSTM

// ------------------------- scratch (static device globals) -------------------------
__device__ float g_embed[Mrows][En];           // 64 MB: materialized gather
__device__ float g_gx[2][Sn][Bn][G4];          // 256 MB: precomputed input-gate projections
__device__ float g_lstm[Bn][Sn][HID];          // 64 MB: bilstm output
__device__ float g_T[Mrows][ATTn];             // 32 MB: tanh(att1) activations
__device__ float g_scores[Bn * Sn];
__device__ float g_alpha[Bn * Sn];
__device__ float g_pooled[Bn][HID];

__device__ __forceinline__ float sigf(float x) { return 1.f / (1.f + expf(-x)); }

__device__ __forceinline__ uint32_t smem_u32(const void* p) {
    return (uint32_t)__cvta_generic_to_shared(p);
}
__device__ __forceinline__ void fma2(unsigned long long& acc, unsigned long long a, unsigned long long b) {
    asm volatile("fma.rn.f32x2 %0, %1, %2, %0;" : "+l"(acc) : "l"(a), "l"(b));
}

// ------------------------- embedding gather: g_embed[s*64+b] = emb[x[b,s]] -------------------------
__global__ __launch_bounds__(128) void gather_kernel(const int* __restrict__ x,
                                                     const float* __restrict__ emb)
{
    int row = blockIdx.x;               // row = s*64 + b
    int s = row >> 6, b = row & 63;
    int v = x[b * Sn + s];
    const float4* src = (const float4*)&emb[(size_t)v * En];
    float4* dst = (float4*)&g_embed[row][0];
    dst[threadIdx.x] = src[threadIdx.x];   // 128 * 16B = 2KB row
}

// ------------------------- GEMM 1: gx = g_embed @ w_ih^T + b_ih + b_hh -------------------------
// M=32768 (row = s*64+b), N=1024, K=512. BM=128, BN=128, BK=16, 256 threads, 8x8 microtile.
// Grid: x = n-tile (8), y = m-stripe (256), z = dir  -> co-resident blocks share the A stripe in L2.
__global__ __launch_bounds__(256) void gemm_gx_kernel(
    const float* __restrict__ wif, const float* __restrict__ bif, const float* __restrict__ bhf,
    const float* __restrict__ wib, const float* __restrict__ bib, const float* __restrict__ bhb)
{
    const int dir = blockIdx.z;
    const float* W  = dir ? wib : wif;
    const float* B1 = dir ? bib : bif;
    const float* B2 = dir ? bhb : bhf;
    float* OUT = &g_gx[dir][0][0][0];

    __shared__ float As[16][128];
    __shared__ float Ws[16][128];

    const int tid = threadIdx.x;
    const int n0 = blockIdx.x * 128;
    const int m0 = blockIdx.y * 128;
    const float* A = &g_embed[0][0];

    float acc[8][8];
    #pragma unroll
    for (int i = 0; i < 8; i++)
        #pragma unroll
        for (int j = 0; j < 8; j++) acc[i][j] = 0.f;

    const int rg = tid >> 4;   // 0..15
    const int cg = tid & 15;   // 0..15

    for (int k0 = 0; k0 < En; k0 += 16) {
        #pragma unroll
        for (int i = 0; i < 2; i++) {
            int e = tid + i * 256;               // 0..511 float4 slots
            int m = e >> 2;
            int k4 = (e & 3) * 4;
            float4 v = *reinterpret_cast<const float4*>(&A[(size_t)(m0 + m) * En + k0 + k4]);
            As[k4 + 0][m] = v.x; As[k4 + 1][m] = v.y; As[k4 + 2][m] = v.z; As[k4 + 3][m] = v.w;
        }
        #pragma unroll
        for (int i = 0; i < 2; i++) {
            int e = tid + i * 256;
            int n = e >> 2;
            int k4 = (e & 3) * 4;
            float4 v = *reinterpret_cast<const float4*>(&W[(size_t)(n0 + n) * En + k0 + k4]);
            Ws[k4 + 0][n] = v.x; Ws[k4 + 1][n] = v.y; Ws[k4 + 2][n] = v.z; Ws[k4 + 3][n] = v.w;
        }
        __syncthreads();
        #pragma unroll
        for (int k = 0; k < 16; k++) {
            float ra[8], rw[8];
            #pragma unroll
            for (int i = 0; i < 8; i++) ra[i] = As[k][rg * 8 + i];
            #pragma unroll
            for (int j = 0; j < 8; j++) rw[j] = Ws[k][cg * 8 + j];
            #pragma unroll
            for (int i = 0; i < 8; i++)
                #pragma unroll
                for (int j = 0; j < 8; j++) acc[i][j] += ra[i] * rw[j];
        }
        __syncthreads();
    }
    #pragma unroll
    for (int i = 0; i < 8; i++) {
        size_t r = (size_t)(m0 + rg * 8 + i);
        #pragma unroll
        for (int j = 0; j < 8; j++) {
            int n = n0 + cg * 8 + j;
            OUT[r * G4 + n] = acc[i][j] + B1[n] + B2[n];
        }
    }
}

// ------------------------- GEMM 2: T = tanh(lstm_out @ att1_w^T + b1) -------------------------
__global__ __launch_bounds__(256) void gemm_att_kernel(
    const float* __restrict__ W, const float* __restrict__ bias)
{
    __shared__ float As[16][128];
    __shared__ float Ws[16][128];

    const int tid = threadIdx.x;
    const int m0 = blockIdx.x * 128;
    const int n0 = blockIdx.y * 128;
    const float* A = &g_lstm[0][0][0];

    float acc[8][8];
    #pragma unroll
    for (int i = 0; i < 8; i++)
        #pragma unroll
        for (int j = 0; j < 8; j++) acc[i][j] = 0.f;

    const int rg = tid >> 4;
    const int cg = tid & 15;

    for (int k0 = 0; k0 < HID; k0 += 16) {
        #pragma unroll
        for (int i = 0; i < 2; i++) {
            int e = tid + i * 256;
            int m = e >> 2;
            int k4 = (e & 3) * 4;
            float4 v = *reinterpret_cast<const float4*>(&A[(size_t)(m0 + m) * HID + k0 + k4]);
            As[k4 + 0][m] = v.x; As[k4 + 1][m] = v.y; As[k4 + 2][m] = v.z; As[k4 + 3][m] = v.w;
        }
        #pragma unroll
        for (int i = 0; i < 2; i++) {
            int e = tid + i * 256;
            int n = e >> 2;
            int k4 = (e & 3) * 4;
            float4 v = *reinterpret_cast<const float4*>(&W[(size_t)(n0 + n) * HID + k0 + k4]);
            Ws[k4 + 0][n] = v.x; Ws[k4 + 1][n] = v.y; Ws[k4 + 2][n] = v.z; Ws[k4 + 3][n] = v.w;
        }
        __syncthreads();
        #pragma unroll
        for (int k = 0; k < 16; k++) {
            float ra[8], rw[8];
            #pragma unroll
            for (int i = 0; i < 8; i++) ra[i] = As[k][rg * 8 + i];
            #pragma unroll
            for (int j = 0; j < 8; j++) rw[j] = Ws[k][cg * 8 + j];
            #pragma unroll
            for (int i = 0; i < 8; i++)
                #pragma unroll
                for (int j = 0; j < 8; j++) acc[i][j] += ra[i] * rw[j];
        }
        __syncthreads();
    }
    #pragma unroll
    for (int i = 0; i < 8; i++) {
        int r = m0 + rg * 8 + i;
        #pragma unroll
        for (int j = 0; j < 8; j++) {
            int n = n0 + cg * 8 + j;
            g_T[r][n] = tanhf(acc[i][j] + bias[n]);
        }
    }
}

// ------------------------- LSTM: cluster-persistent, SMEM-resident weights -------------------------
// grid = (64, 2): x = bg*8 + rank (cluster of 8 along x), y = dir. 256 threads.
// Cluster (dir, bg) handles 8 batches. CTA rank r owns hidden units j in [r*32, r*32+32),
// keeps its 4 gates x 32 j x 256 k weights (130 KB, padded) in SMEM, computes gates for its
// 8 batches with packed f32x2 FMA, then broadcasts its 32 h-values per batch to all 8 CTAs
// via DSMEM. One cluster barrier per step; h double-buffered.
//
// Thread layout: tid = b*32 + j  (warp == batch, lane == j). Weight LDS: per 8-lane phase,
// 8 consecutive j at row stride 130 u64 (=4 banks) -> 32 distinct banks, conflict-free.
// h LDS: whole warp reads the same address -> broadcast. gx LDG: 128B contiguous per warp.
#define LSTM_W_U64   (4 * 32 * 130)                       // padded weights, in u64
#define LSTM_SMEM    (LSTM_W_U64 * 8 + 2 * 8 * 256 * 4)   // 133120 + 16384 = 149504 B

__global__ __launch_bounds__(256, 1) __cluster_dims__(CLU, 1, 1)
void lstm_cluster_kernel(const float* __restrict__ whf, const float* __restrict__ whb)
{
    extern __shared__ unsigned long long sm[];
    unsigned long long (*w2)[32][130] = (unsigned long long(*)[32][130])sm;
    float* hb = (float*)(sm + LSTM_W_U64);    // hbuf[2][8][256]

    const int dir = blockIdx.y;
    const int cx  = blockIdx.x;
    const int bg  = cx >> 3;      // batch group 0..7
    const int r   = cx & 7;       // cluster rank
    const int tid = threadIdx.x;
    const int b   = tid >> 5;     // 0..7
    const int j   = tid & 31;     // 0..31

    // Load this CTA's weight slice: rows gate*256 + r*32 + jj, k = 0..255
    const float* W = dir ? whb : whf;
    for (int e = tid; e < 4 * 32 * 64; e += 256) {   // float4 granularity
        int g  = e >> 11;
        int jj = (e >> 6) & 31;
        int c4 = e & 63;
        float4 v = *(const float4*)&W[(size_t)(g * 256 + r * 32 + jj) * 256 + c4 * 4];
        *(float4*)&w2[g][jj][c4 * 2] = v;
    }
    for (int e = tid; e < 2 * 8 * 256; e += 256) hb[e] = 0.f;
    __syncthreads();
    asm volatile("barrier.cluster.arrive.aligned;" ::: "memory");
    asm volatile("barrier.cluster.wait.aligned;"  ::: "memory");

    // DSMEM destinations: peer hbuf base addresses
    uint32_t hb_local = smem_u32(hb);
    uint32_t dst[CLU];
    #pragma unroll
    for (int p = 0; p < CLU; p++) {
        uint32_t a;
        asm("mapa.shared::cluster.u32 %0, %1, %2;" : "=r"(a) : "r"(hb_local), "r"(p));
        dst[p] = a;
    }

    const unsigned long long* wrow0 = &w2[0][j][0];
    const unsigned long long* wrow1 = &w2[1][j][0];
    const unsigned long long* wrow2 = &w2[2][j][0];
    const unsigned long long* wrow3 = &w2[3][j][0];

    const int bglob = bg * 8 + b;
    const float* gxbase = &g_gx[dir][0][0][0];
    float c = 0.f;
    int cur = 0;

    for (int t = 0; t < Sn; t++) {
        const int s = dir ? (Sn - 1 - t) : t;

        // prefetch gx early (DRAM latency hidden under the acc loop)
        const float* gp = gxbase + ((size_t)s * Bn + bglob) * G4 + r * 32 + j;
        float pre_i = gp[0 * Hn], pre_f = gp[1 * Hn], pre_g = gp[2 * Hn], pre_o = gp[3 * Hn];

        const ulonglong2* hp = (const ulonglong2*)(hb + (cur * 8 + b) * 256);
        const ulonglong2* p0 = (const ulonglong2*)wrow0;
        const ulonglong2* p1 = (const ulonglong2*)wrow1;
        const ulonglong2* p2 = (const ulonglong2*)wrow2;
        const ulonglong2* p3 = (const ulonglong2*)wrow3;

        unsigned long long ai = 0ull, af = 0ull, ag = 0ull, ao = 0ull;
        #pragma unroll 8
        for (int kq = 0; kq < 64; kq++) {
            ulonglong2 h2 = hp[kq];
            ulonglong2 v0 = p0[kq];
            ulonglong2 v1 = p1[kq];
            ulonglong2 v2 = p2[kq];
            ulonglong2 v3 = p3[kq];
            fma2(ai, v0.x, h2.x); fma2(ai, v0.y, h2.y);
            fma2(af, v1.x, h2.x); fma2(af, v1.y, h2.y);
            fma2(ag, v2.x, h2.x); fma2(ag, v2.y, h2.y);
            fma2(ao, v3.x, h2.x); fma2(ao, v3.y, h2.y);
        }

        float2 qi = *(float2*)&ai, qf = *(float2*)&af, qg = *(float2*)&ag, qo = *(float2*)&ao;
        float I = sigf(pre_i + qi.x + qi.y);
        float F = sigf(pre_f + qf.x + qf.y);
        float G = tanhf(pre_g + qg.x + qg.y);
        float O = sigf(pre_o + qo.x + qo.y);
        c = F * c + I * G;
        float h = O * tanhf(c);

        g_lstm[bglob][s][dir * Hn + r * 32 + j] = h;

        const int nxt = cur ^ 1;
        uint32_t off = (uint32_t)(((nxt * 8 + b) * 256 + r * 32 + j) * 4);
        #pragma unroll
        for (int p = 0; p < CLU; p++)
            asm volatile("st.shared::cluster.f32 [%0], %1;" :: "r"(dst[p] + off), "f"(h) : "memory");

        asm volatile("barrier.cluster.arrive.aligned;" ::: "memory");
        asm volatile("barrier.cluster.wait.aligned;"  ::: "memory");
        cur = nxt;
    }
}

// ------------------------- scores = T @ UT -------------------------
__global__ __launch_bounds__(256) void score_kernel(const float* __restrict__ UT)
{
    int row = blockIdx.x * 8 + (threadIdx.x >> 5);
    int lane = threadIdx.x & 31;
    float s = 0.f;
    #pragma unroll
    for (int i = 0; i < 8; i++) s += g_T[row][lane + i * 32] * UT[lane + i * 32];
    #pragma unroll
    for (int o = 16; o > 0; o >>= 1) s += __shfl_xor_sync(0xffffffffu, s, o);
    if (lane == 0) g_scores[row] = s;
}

// ------------------------- softmax over S per batch -------------------------
__global__ __launch_bounds__(512) void softmax_kernel(float* alpha_out)
{
    int b = blockIdx.x, s = threadIdx.x;
    float v = g_scores[b * Sn + s];
    __shared__ float red[16];

    float m = v;
    #pragma unroll
    for (int o = 16; o > 0; o >>= 1) m = fmaxf(m, __shfl_xor_sync(0xffffffffu, m, o));
    if ((s & 31) == 0) red[s >> 5] = m;
    __syncthreads();
    if (s < 32) {
        float t = (s < 16) ? red[s] : -3.4e38f;
        #pragma unroll
        for (int o = 8; o > 0; o >>= 1) t = fmaxf(t, __shfl_xor_sync(0xffffffffu, t, o));
        if (s == 0) red[0] = t;
    }
    __syncthreads();
    m = red[0];
    __syncthreads();

    float e = expf(v - m);
    float sum = e;
    #pragma unroll
    for (int o = 16; o > 0; o >>= 1) sum += __shfl_xor_sync(0xffffffffu, sum, o);
    if ((s & 31) == 0) red[s >> 5] = sum;
    __syncthreads();
    if (s < 32) {
        float t = (s < 16) ? red[s] : 0.f;
        #pragma unroll
        for (int o = 8; o > 0; o >>= 1) t += __shfl_xor_sync(0xffffffffu, t, o);
        if (s == 0) red[0] = t;
    }
    __syncthreads();
    float a = e / red[0];
    g_alpha[b * Sn + s] = a;
    if (alpha_out) alpha_out[b * Sn + s] = a;
}

// ------------------------- pooled = sum_s alpha[b,s] * lstm_out[b,s,:] -------------------------
__global__ __launch_bounds__(512) void pooled_kernel()
{
    int b = blockIdx.x, h = threadIdx.x;
    __shared__ float al[Sn];
    al[h] = g_alpha[b * Sn + h];
    __syncthreads();
    float acc = 0.f;
    #pragma unroll 8
    for (int s = 0; s < Sn; s++) acc += al[s] * g_lstm[b][s][h];
    g_pooled[b][h] = acc;
}

// ------------------------- logit = pooled @ att2_w^T + b2 -------------------------
__global__ __launch_bounds__(320) void logit_kernel(
    const float* __restrict__ w2, const float* __restrict__ b2, float* out)
{
    int b = blockIdx.x;
    int c = threadIdx.x >> 5;     // 0..9
    int lane = threadIdx.x & 31;
    float acc = 0.f;
    #pragma unroll
    for (int i = 0; i < 16; i++)
        acc += g_pooled[b][lane + i * 32] * w2[c * HID + lane + i * 32];
    #pragma unroll
    for (int o = 16; o > 0; o >>= 1) acc += __shfl_xor_sync(0xffffffffu, acc, o);
    if (lane == 0 && out) out[b * Cn + c] = acc + b2[c];
}

// ------------------------- launch -------------------------
extern "C" void kernel_launch(void* const* d_in, const int* in_sizes, int n_in,
                              void* d_out, int out_size)
{
    const int*   x   = (const int*)d_in[0];
    const float* emb = (const float*)d_in[1];
    const float* wif = (const float*)d_in[2];
    const float* whf = (const float*)d_in[3];
    const float* bif = (const float*)d_in[4];
    const float* bhf = (const float*)d_in[5];
    const float* wib = (const float*)d_in[6];
    const float* whb = (const float*)d_in[7];
    const float* bib = (const float*)d_in[8];
    const float* bhb = (const float*)d_in[9];
    const float* a1w = (const float*)d_in[10];
    const float* a1b = (const float*)d_in[11];
    const float* ut  = (const float*)d_in[12];
    const float* a2w = (const float*)d_in[13];
    const float* a2b = (const float*)d_in[14];
    float* out = (float*)d_out;

    // output layout: (logit[64*10], alpha[64*512]) flattened in tuple order
    float* logit_ptr = nullptr;
    float* alpha_ptr = nullptr;
    if (out_size >= Bn * Cn + Bn * Sn) { logit_ptr = out; alpha_ptr = out + Bn * Cn; }
    else if (out_size == Bn * Sn)      { alpha_ptr = out; }
    else                                { logit_ptr = out; }

    static int smem_set = 0;
    if (!smem_set) {
        cudaFuncSetAttribute(lstm_cluster_kernel,
                             cudaFuncAttributeMaxDynamicSharedMemorySize, LSTM_SMEM);
        smem_set = 1;
    }

    gather_kernel<<<Mrows, 128>>>(x, emb);
    gemm_gx_kernel<<<dim3(G4 / 128, Mrows / 128, 2), 256>>>(wif, bif, bhf, wib, bib, bhb);
    lstm_cluster_kernel<<<dim3(64, 2), 256, LSTM_SMEM>>>(whf, whb);
    gemm_att_kernel<<<dim3(Mrows / 128, ATTn / 128), 256>>>(a1w, a1b);
    score_kernel<<<Mrows / 8, 256>>>(ut);
    softmax_kernel<<<Bn, 512>>>(alpha_ptr);
    pooled_kernel<<<Bn, 512>>>();
    logit_kernel<<<Bn, 320>>>(a2w, a2b, logit_ptr);
}